// round 11
// baseline (speedup 1.0000x reference)
#include <cuda_runtime.h>
#include <cuda_bf16.h>
#include <stdint.h>
#include <math.h>

// ---------------------------------------------------------------------------
// ConvCrossAttention, fully tensorized (mma.sync bf16, 3xBF16 hi/lo split).
// R11: MMA issue reordered (term-major / paired tiles) to break accumulator
// dependency chains. Math identical to R10 (per-acc term order preserved).
// ---------------------------------------------------------------------------

__device__ unsigned g_yq [2*16*256*1024];  // dwconv q path  [s][b][c][p]
__device__ unsigned g_ykv[2*16*256*256];   // dwconv kv path [s][b][c][j]
__device__ unsigned g_q  [2*16*8*1024*64]; // [s][b][h][p][d]   (scale folded)
__device__ unsigned g_k  [2*16*8*256*64];
__device__ unsigned g_v  [2*16*8*256*64];
__device__ unsigned g_o  [2*16*512*1024];  // attn out [s][b][c=h*64+d][p]
__device__ __nv_bfloat16 g_wq_hi [2*512*256],  g_wq_lo [2*512*256];
__device__ __nv_bfloat16 g_wkv_hi[2*1024*256], g_wkv_lo[2*1024*256];
__device__ __nv_bfloat16 g_wo_hi [2*256*512],  g_wo_lo [2*256*512];

__device__ __forceinline__ unsigned pack_pair(float v)
{
    __nv_bfloat162 p;
    p.x = __float2bfloat16(v);
    p.y = __float2bfloat16(v - __bfloat162float(p.x));
    return *(unsigned*)&p;
}

__device__ __forceinline__ void pack2(float a, float b, unsigned& hi, unsigned& lo)
{
    __nv_bfloat162 h = __floats2bfloat162_rn(a, b);
    __nv_bfloat162 l = __floats2bfloat162_rn(a - __bfloat162float(h.x),
                                             b - __bfloat162float(h.y));
    hi = *(unsigned*)&h;
    lo = *(unsigned*)&l;
}

// ---------------------------------------------------------------------------
__global__ void split_all_kernel(const float* __restrict__ wq0, const float* __restrict__ wq1,
                                 const float* __restrict__ wkv0, const float* __restrict__ wkv1,
                                 const float* __restrict__ wo0, const float* __restrict__ wo1)
{
    int i = blockIdx.x * blockDim.x + threadIdx.x;
    const float* src;
    __nv_bfloat16 *hi, *lo;
    int dst;
    float scale = 1.0f;
    if (i < 262144) {
        int sphase = i >= 131072;
        src = sphase ? wq1 + (i - 131072) : wq0 + i;
        hi = g_wq_hi; lo = g_wq_lo; dst = i; scale = 0.125f;
    } else if (i < 786432) {
        int j = i - 262144;
        int sphase = j >= 262144;
        src = sphase ? wkv1 + (j - 262144) : wkv0 + j;
        hi = g_wkv_hi; lo = g_wkv_lo; dst = j;
    } else {
        int j = i - 786432;
        int sphase = j >= 131072;
        src = sphase ? wo1 + (j - 131072) : wo0 + j;
        hi = g_wo_hi; lo = g_wo_lo; dst = j;
    }
    float v = *src * scale;
    __nv_bfloat16 h = __float2bfloat16(v);
    hi[dst] = h;
    lo[dst] = __float2bfloat16(v - __bfloat162float(h));
}

// ---------------------------------------------------------------------------
__global__ void dwconv2_kernel(const float* __restrict__ x0, const float* __restrict__ x1,
                               const float* __restrict__ dw0, const float* __restrict__ g0,
                               const float* __restrict__ b0, const float* __restrict__ rm0,
                               const float* __restrict__ rv0,
                               const float* __restrict__ dw1, const float* __restrict__ g1,
                               const float* __restrict__ b1, const float* __restrict__ rm1,
                               const float* __restrict__ rv1,
                               int dst_kv, int stride, int OH)
{
    int idx = blockIdx.x * blockDim.x + threadIdx.x;
    int total = 16 * 256 * OH * OH;
    if (idx >= total) return;
    int sp = blockIdx.y;
    const float* x  = sp ? x1 : x0;
    const float* dw = sp ? dw1 : dw0;
    const float* gam = sp ? g1 : g0;
    const float* bet = sp ? b1 : b0;
    const float* rm = sp ? rm1 : rm0;
    const float* rv = sp ? rv1 : rv0;

    int ox = idx % OH; int t = idx / OH;
    int oy = t % OH;   t /= OH;
    int c = t & 255;   int b = t >> 8;

    const float* xp = x + ((b << 8) | c) * 1024;
    const float* w  = dw + c * 9;
    int iy0 = oy * stride - 1, ix0 = ox * stride - 1;
    float acc = 0.f;
#pragma unroll
    for (int ky = 0; ky < 3; ky++) {
        int iy = iy0 + ky;
        if ((unsigned)iy < 32u) {
#pragma unroll
            for (int kx = 0; kx < 3; kx++) {
                int ix = ix0 + kx;
                if ((unsigned)ix < 32u) acc += xp[iy * 32 + ix] * w[ky * 3 + kx];
            }
        }
    }
    float inv = gam[c] * rsqrtf(rv[c] + 1e-5f);
    float r = acc * inv + (bet[c] - rm[c] * inv);
    unsigned* y = dst_kv ? g_ykv : g_yq;
    y[sp * total + idx] = pack_pair(r);
}

// ---------------------------------------------------------------------------
// MMA primitives
// ---------------------------------------------------------------------------
#define MMA_BF16(d, a, b) asm volatile( \
    "mma.sync.aligned.m16n8k16.row.col.f32.bf16.bf16.f32 " \
    "{%0,%1,%2,%3}, {%4,%5,%6,%7}, {%8,%9}, {%0,%1,%2,%3};" \
    : "+f"(d[0]), "+f"(d[1]), "+f"(d[2]), "+f"(d[3]) \
    : "r"(a[0]), "r"(a[1]), "r"(a[2]), "r"(a[3]), "r"(b[0]), "r"(b[1]))

#define LDSM_X4(R, p) { unsigned _ad = (unsigned)__cvta_generic_to_shared(p); \
    asm volatile("ldmatrix.sync.aligned.m8n8.x4.shared.b16 {%0,%1,%2,%3}, [%4];" \
        : "=r"(R[0]), "=r"(R[1]), "=r"(R[2]), "=r"(R[3]) : "r"(_ad)); }

#define LDSM_X4T(R, p) { unsigned _ad = (unsigned)__cvta_generic_to_shared(p); \
    asm volatile("ldmatrix.sync.aligned.m8n8.x4.trans.shared.b16 {%0,%1,%2,%3}, [%4];" \
        : "=r"(R[0]), "=r"(R[1]), "=r"(R[2]), "=r"(R[3]) : "r"(_ad)); }

#define CP_ASYNC16(smem_u32, gptr) \
    asm volatile("cp.async.cg.shared.global [%0], [%1], 16;" :: "r"(smem_u32), "l"(gptr))
#define CP_COMMIT() asm volatile("cp.async.commit_group;")
#define CP_WAIT0()  asm volatile("cp.async.wait_group 0;")

// ---------------------------------------------------------------------------
// Pipelined tensor-core GEMM (3xBF16 split): C[z] = W [M,K] @ B[z] [K,N].
// 128x128 tile, BK=32, 256 threads (8 warps 2x4), warp tile 64x32.
// MMA issue is term-major: 16 independent accumulators between dependents.
// ---------------------------------------------------------------------------
#define BM 128
#define BN 128
#define BK 32
#define SA_STR 40
#define SB_STR 136
#define A_PLANE 10240
#define B_PLANE 8704
#define BUF_BYTES 37888
#define GEMM_SMEM 75776

__global__ __launch_bounds__(256) void mma_gemm(int M, int N, int K, int mode,
                                                float* __restrict__ Ob,
                                                const float* __restrict__ bias0,
                                                const float* __restrict__ bias1)
{
    extern __shared__ char gsm[];
    unsigned* sC = (unsigned*)gsm;

    int z = blockIdx.z, s = z >> 4;
    const __nv_bfloat16 *Ah, *Al;
    const unsigned* Bp;
    if (mode == 0) {
        Ah = g_wq_hi  + s * 512 * 256;  Al = g_wq_lo  + s * 512 * 256;
        Bp = g_yq  + (long)z * 256 * 1024;
    } else if (mode == 1) {
        Ah = g_wkv_hi + s * 1024 * 256; Al = g_wkv_lo + s * 1024 * 256;
        Bp = g_ykv + (long)z * 256 * 256;
    } else {
        Ah = g_wo_hi  + s * 256 * 512;  Al = g_wo_lo  + s * 256 * 512;
        Bp = g_o   + (long)z * 512 * 1024;
    }

    int m0 = blockIdx.y * BM, n0 = blockIdx.x * BN;
    int tid = threadIdx.x, lane = tid & 31, wid = tid >> 5;
    int wm = wid >> 2, wn = wid & 3;

    float acc[4][4][4] = {};

    int arow = tid >> 2, acol = (tid & 3) * 8;
    int lr = lane & 15, lc = (lane >> 4) * 8;
    int brow2 = (lane & 7) + ((lane >> 3) & 1) * 8;
    int bcol2 = (lane >> 4) * 8;

    __nv_bfloat16* pAh[2] = {(__nv_bfloat16*)gsm, (__nv_bfloat16*)(gsm + BUF_BYTES)};
    __nv_bfloat16* pAl[2] = {(__nv_bfloat16*)(gsm + A_PLANE), (__nv_bfloat16*)(gsm + BUF_BYTES + A_PLANE)};
    __nv_bfloat16* pBh[2] = {(__nv_bfloat16*)(gsm + 2*A_PLANE), (__nv_bfloat16*)(gsm + BUF_BYTES + 2*A_PLANE)};
    __nv_bfloat16* pBl[2] = {(__nv_bfloat16*)(gsm + 2*A_PLANE + B_PLANE), (__nv_bfloat16*)(gsm + BUF_BYTES + 2*A_PLANE + B_PLANE)};

    uint4 stB[4];
    int nk = K / BK;

    int bR[2], bC[2];
#pragma unroll
    for (int j = 0; j < 2; j++) { int sj = tid + 256 * j; bR[j] = sj >> 4; bC[j] = (sj & 15) * 8; }

    // ---- prologue: buffer 0
    {
#pragma unroll
        for (int r = 0; r < 2; r++) {
            unsigned d0 = (unsigned)__cvta_generic_to_shared(&pAh[0][(arow + 64 * r) * SA_STR + acol]);
            unsigned d1 = (unsigned)__cvta_generic_to_shared(&pAl[0][(arow + 64 * r) * SA_STR + acol]);
            CP_ASYNC16(d0, &Ah[(long)(m0 + arow + 64 * r) * K + acol]);
            CP_ASYNC16(d1, &Al[(long)(m0 + arow + 64 * r) * K + acol]);
        }
        CP_COMMIT();
#pragma unroll
        for (int j = 0; j < 2; j++) {
            const unsigned* src = &Bp[(long)bR[j] * N + n0 + bC[j]];
            stB[2 * j]     = *(const uint4*)src;
            stB[2 * j + 1] = *(const uint4*)(src + 4);
        }
#pragma unroll
        for (int j = 0; j < 2; j++) {
            uint4 u0 = stB[2 * j], u1 = stB[2 * j + 1];
            uint4 hv = make_uint4(__byte_perm(u0.x, u0.y, 0x5410), __byte_perm(u0.z, u0.w, 0x5410),
                                  __byte_perm(u1.x, u1.y, 0x5410), __byte_perm(u1.z, u1.w, 0x5410));
            uint4 lv = make_uint4(__byte_perm(u0.x, u0.y, 0x7632), __byte_perm(u0.z, u0.w, 0x7632),
                                  __byte_perm(u1.x, u1.y, 0x7632), __byte_perm(u1.z, u1.w, 0x7632));
            *(uint4*)&pBh[0][bR[j] * SB_STR + bC[j]] = hv;
            *(uint4*)&pBl[0][bR[j] * SB_STR + bC[j]] = lv;
        }
        CP_WAIT0();
        __syncthreads();
    }

    for (int i = 0; i < nk; i++) {
        int cur = i & 1, nxt = cur ^ 1;
        bool has_next = (i + 1 < nk);
        if (has_next) {
            int k0 = (i + 1) * BK;
#pragma unroll
            for (int r = 0; r < 2; r++) {
                unsigned d0 = (unsigned)__cvta_generic_to_shared(&pAh[nxt][(arow + 64 * r) * SA_STR + acol]);
                unsigned d1 = (unsigned)__cvta_generic_to_shared(&pAl[nxt][(arow + 64 * r) * SA_STR + acol]);
                CP_ASYNC16(d0, &Ah[(long)(m0 + arow + 64 * r) * K + k0 + acol]);
                CP_ASYNC16(d1, &Al[(long)(m0 + arow + 64 * r) * K + k0 + acol]);
            }
            CP_COMMIT();
#pragma unroll
            for (int j = 0; j < 2; j++) {
                const unsigned* src = &Bp[(long)(k0 + bR[j]) * N + n0 + bC[j]];
                stB[2 * j]     = *(const uint4*)src;
                stB[2 * j + 1] = *(const uint4*)(src + 4);
            }
        }

        // compute buffer cur — term-major MMA issue (dep distance 16)
#pragma unroll
        for (int kk = 0; kk < BK; kk += 16) {
            unsigned ah[4][4], al[4][4], bh4[2][4], bl4[2][4];
#pragma unroll
            for (int mi = 0; mi < 4; mi++) {
                LDSM_X4(ah[mi], &pAh[cur][(wm * 64 + mi * 16 + lr) * SA_STR + kk + lc]);
                LDSM_X4(al[mi], &pAl[cur][(wm * 64 + mi * 16 + lr) * SA_STR + kk + lc]);
            }
#pragma unroll
            for (int ni2 = 0; ni2 < 2; ni2++) {
                LDSM_X4T(bh4[ni2], &pBh[cur][(kk + brow2) * SB_STR + wn * 32 + ni2 * 16 + bcol2]);
                LDSM_X4T(bl4[ni2], &pBl[cur][(kk + brow2) * SB_STR + wn * 32 + ni2 * 16 + bcol2]);
            }
            // term hh
#pragma unroll
            for (int mi = 0; mi < 4; mi++)
#pragma unroll
                for (int ni = 0; ni < 4; ni++) {
                    unsigned* bh = bh4[ni >> 1] + (ni & 1) * 2;
                    MMA_BF16(acc[mi][ni], ah[mi], bh);
                }
            // term hl
#pragma unroll
            for (int mi = 0; mi < 4; mi++)
#pragma unroll
                for (int ni = 0; ni < 4; ni++) {
                    unsigned* bl = bl4[ni >> 1] + (ni & 1) * 2;
                    MMA_BF16(acc[mi][ni], ah[mi], bl);
                }
            // term lh
#pragma unroll
            for (int mi = 0; mi < 4; mi++)
#pragma unroll
                for (int ni = 0; ni < 4; ni++) {
                    unsigned* bh = bh4[ni >> 1] + (ni & 1) * 2;
                    MMA_BF16(acc[mi][ni], al[mi], bh);
                }
        }

        if (has_next) {
#pragma unroll
            for (int j = 0; j < 2; j++) {
                uint4 u0 = stB[2 * j], u1 = stB[2 * j + 1];
                uint4 hv = make_uint4(__byte_perm(u0.x, u0.y, 0x5410), __byte_perm(u0.z, u0.w, 0x5410),
                                      __byte_perm(u1.x, u1.y, 0x5410), __byte_perm(u1.z, u1.w, 0x5410));
                uint4 lv = make_uint4(__byte_perm(u0.x, u0.y, 0x7632), __byte_perm(u0.z, u0.w, 0x7632),
                                      __byte_perm(u1.x, u1.y, 0x7632), __byte_perm(u1.z, u1.w, 0x7632));
                *(uint4*)&pBh[nxt][bR[j] * SB_STR + bC[j]] = hv;
                *(uint4*)&pBl[nxt][bR[j] * SB_STR + bC[j]] = lv;
            }
            CP_WAIT0();
        }
        __syncthreads();
    }

    int r = lane >> 2, cc = (lane & 3) * 2;
    if (mode == 2) {
        const float* bias = s ? bias1 : bias0;
#pragma unroll
        for (int mi = 0; mi < 4; mi++)
#pragma unroll
            for (int ni = 0; ni < 4; ni++)
#pragma unroll
                for (int half = 0; half < 2; half++) {
                    int m = m0 + wm * 64 + mi * 16 + r + half * 8;
                    int n = n0 + wn * 32 + ni * 8 + cc;
                    float bv = bias[m];
                    float2 v = make_float2(acc[mi][ni][half * 2] + bv,
                                           acc[mi][ni][half * 2 + 1] + bv);
                    *(float2*)&Ob[((long)z * M + m) * N + n] = v;
                }
    } else {
#pragma unroll
        for (int mi = 0; mi < 4; mi++)
#pragma unroll
            for (int ni = 0; ni < 4; ni++)
#pragma unroll
                for (int half = 0; half < 2; half++) {
                    int ml = wm * 64 + mi * 16 + r + half * 8;
                    int nl = wn * 32 + ni * 8 + cc;
                    sC[ml * 129 + nl]     = pack_pair(acc[mi][ni][half * 2]);
                    sC[ml * 129 + nl + 1] = pack_pair(acc[mi][ni][half * 2 + 1]);
                }
        __syncthreads();

        int n = tid & 127, hh = tid >> 7;
        int mrow = m0 + hh * 64;
        unsigned* dst;
        long base;
        if (mode == 0) {
            dst = g_q;
            base = ((long)(z * 8 + (mrow >> 6)) * 1024 + n0 + n) * 64;
        } else if (mrow < 512) {
            dst = g_k;
            base = ((long)(z * 8 + (mrow >> 6)) * 256 + n0 + n) * 64;
        } else {
            dst = g_v;
            base = ((long)(z * 8 + ((mrow - 512) >> 6)) * 256 + n0 + n) * 64;
        }
#pragma unroll
        for (int d4 = 0; d4 < 64; d4 += 4) {
            uint4 t;
            t.x = sC[(hh * 64 + d4 + 0) * 129 + n];
            t.y = sC[(hh * 64 + d4 + 1) * 129 + n];
            t.z = sC[(hh * 64 + d4 + 2) * 129 + n];
            t.w = sC[(hh * 64 + d4 + 3) * 129 + n];
            *(uint4*)&dst[base + d4] = t;
        }
    }
}

// ---------------------------------------------------------------------------
// Tensorized cross attention. MMA issue paired across tiles + term-major.
// ---------------------------------------------------------------------------
#define ATT_SMEM 184320

__global__ __launch_bounds__(256) void attn_kernel()
{
    extern __shared__ char smx[];
    __nv_bfloat16* Kh = (__nv_bfloat16*)(smx);
    __nv_bfloat16* Kl = (__nv_bfloat16*)(smx + 36864);
    __nv_bfloat16* Vh = (__nv_bfloat16*)(smx + 73728);
    __nv_bfloat16* Vl = (__nv_bfloat16*)(smx + 110592);
    __nv_bfloat16* Qh = (__nv_bfloat16*)(smx + 147456);
    __nv_bfloat16* Ql = (__nv_bfloat16*)(smx + 165888);
    float*        Ost = (float*)(smx + 147456);

    int bid = blockIdx.x;
    int qt = bid & 7, bhs = bid >> 3;
    int s = bhs >> 7, bh = bhs & 127, h = bh & 7, b = bh >> 3;

    const unsigned* qp = g_q + ((long)(s * 128 + bh) * 1024 + qt * 128) * 64;
    const unsigned* kp = g_k + (long)((1 - s) * 128 + bh) * 256 * 64;
    const unsigned* vp = g_v + (long)((1 - s) * 128 + bh) * 256 * 64;

    int tid = threadIdx.x, lane = tid & 31, w = tid >> 5;

    for (int c = tid; c < 4096; c += 256) {
        int row = c >> 4, seg = (c & 15) * 4;
        uint4 u = *(const uint4*)&kp[row * 64 + seg];
        *(uint2*)&Kh[row * 72 + seg] = make_uint2(__byte_perm(u.x, u.y, 0x5410), __byte_perm(u.z, u.w, 0x5410));
        *(uint2*)&Kl[row * 72 + seg] = make_uint2(__byte_perm(u.x, u.y, 0x7632), __byte_perm(u.z, u.w, 0x7632));
        u = *(const uint4*)&vp[row * 64 + seg];
        *(uint2*)&Vh[row * 72 + seg] = make_uint2(__byte_perm(u.x, u.y, 0x5410), __byte_perm(u.z, u.w, 0x5410));
        *(uint2*)&Vl[row * 72 + seg] = make_uint2(__byte_perm(u.x, u.y, 0x7632), __byte_perm(u.z, u.w, 0x7632));
    }
    for (int c = tid; c < 2048; c += 256) {
        int row = c >> 4, seg = (c & 15) * 4;
        uint4 u = *(const uint4*)&qp[row * 64 + seg];
        *(uint2*)&Qh[row * 72 + seg] = make_uint2(__byte_perm(u.x, u.y, 0x5410), __byte_perm(u.z, u.w, 0x5410));
        *(uint2*)&Ql[row * 72 + seg] = make_uint2(__byte_perm(u.x, u.y, 0x7632), __byte_perm(u.z, u.w, 0x7632));
    }
    __syncthreads();

    // ---- S = Q @ K^T : paired K-tiles, term-major (4 accs in flight)
    float sreg[32][4];
#pragma unroll
    for (int nt = 0; nt < 32; nt++) {
        sreg[nt][0] = 0.f; sreg[nt][1] = 0.f; sreg[nt][2] = 0.f; sreg[nt][3] = 0.f;
    }
    int r0 = w * 16;
    int krow = (lane & 7) + ((lane >> 4) << 3);
    for (int kk = 0; kk < 4; kk++) {
        unsigned ah[4], al[4];
        int qoff = (r0 + (lane & 15)) * 72 + kk * 16 + (lane >> 4) * 8;
        LDSM_X4(ah, &Qh[qoff]);
        LDSM_X4(al, &Ql[qoff]);
        int koff = kk * 16 + ((lane >> 3) & 1) * 8;
#pragma unroll
        for (int nt4 = 0; nt4 < 8; nt4++) {
            unsigned khA[4], klA[4], khB[4], klB[4];
            LDSM_X4(khA, &Kh[((2 * nt4) * 16 + krow) * 72 + koff]);
            LDSM_X4(klA, &Kl[((2 * nt4) * 16 + krow) * 72 + koff]);
            LDSM_X4(khB, &Kh[((2 * nt4 + 1) * 16 + krow) * 72 + koff]);
            LDSM_X4(klB, &Kl[((2 * nt4 + 1) * 16 + krow) * 72 + koff]);
            float* s0 = sreg[4 * nt4 + 0];
            float* s1 = sreg[4 * nt4 + 1];
            float* s2 = sreg[4 * nt4 + 2];
            float* s3 = sreg[4 * nt4 + 3];
            // term hh
            MMA_BF16(s0, ah, (khA + 0)); MMA_BF16(s1, ah, (khA + 2));
            MMA_BF16(s2, ah, (khB + 0)); MMA_BF16(s3, ah, (khB + 2));
            // term hl
            MMA_BF16(s0, ah, (klA + 0)); MMA_BF16(s1, ah, (klA + 2));
            MMA_BF16(s2, ah, (klB + 0)); MMA_BF16(s3, ah, (klB + 2));
            // term lh
            MMA_BF16(s0, al, (khA + 0)); MMA_BF16(s1, al, (khA + 2));
            MMA_BF16(s2, al, (khB + 0)); MMA_BF16(s3, al, (khB + 2));
        }
    }

    // ---- softmax on fragments
    float inv0, inv1;
    {
        float m0 = -1e30f, m1 = -1e30f;
#pragma unroll
        for (int nt = 0; nt < 32; nt++) {
            m0 = fmaxf(m0, fmaxf(sreg[nt][0], sreg[nt][1]));
            m1 = fmaxf(m1, fmaxf(sreg[nt][2], sreg[nt][3]));
        }
        m0 = fmaxf(m0, __shfl_xor_sync(0xffffffffu, m0, 1));
        m0 = fmaxf(m0, __shfl_xor_sync(0xffffffffu, m0, 2));
        m1 = fmaxf(m1, __shfl_xor_sync(0xffffffffu, m1, 1));
        m1 = fmaxf(m1, __shfl_xor_sync(0xffffffffu, m1, 2));
        float s0 = 0.f, s1 = 0.f;
#pragma unroll
        for (int nt = 0; nt < 32; nt++) {
            float e0 = __expf(sreg[nt][0] - m0); sreg[nt][0] = e0; s0 += e0;
            float e1 = __expf(sreg[nt][1] - m0); sreg[nt][1] = e1; s0 += e1;
            float e2 = __expf(sreg[nt][2] - m1); sreg[nt][2] = e2; s1 += e2;
            float e3 = __expf(sreg[nt][3] - m1); sreg[nt][3] = e3; s1 += e3;
        }
        s0 += __shfl_xor_sync(0xffffffffu, s0, 1);
        s0 += __shfl_xor_sync(0xffffffffu, s0, 2);
        s1 += __shfl_xor_sync(0xffffffffu, s1, 1);
        s1 += __shfl_xor_sync(0xffffffffu, s1, 2);
        inv0 = 1.f / s0;
        inv1 = 1.f / s1;
    }

    // ---- O = P @ V : paired d-tiles, term-major (4 accs in flight)
    float oreg[8][4] = {};
#pragma unroll
    for (int kt = 0; kt < 16; kt++) {
        unsigned pah[4], pal[4];
        pack2(sreg[2 * kt][0],     sreg[2 * kt][1],     pah[0], pal[0]);
        pack2(sreg[2 * kt][2],     sreg[2 * kt][3],     pah[1], pal[1]);
        pack2(sreg[2 * kt + 1][0], sreg[2 * kt + 1][1], pah[2], pal[2]);
        pack2(sreg[2 * kt + 1][2], sreg[2 * kt + 1][3], pah[3], pal[3]);
        int vrow = kt * 16 + (lane & 7) + ((lane >> 3) & 1) * 8;
        int vcol = (lane >> 4) << 3;
#pragma unroll
        for (int np = 0; np < 2; np++) {
            unsigned vhA[4], vlA[4], vhB[4], vlB[4];
            LDSM_X4T(vhA, &Vh[vrow * 72 + (2 * np) * 16 + vcol]);
            LDSM_X4T(vlA, &Vl[vrow * 72 + (2 * np) * 16 + vcol]);
            LDSM_X4T(vhB, &Vh[vrow * 72 + (2 * np + 1) * 16 + vcol]);
            LDSM_X4T(vlB, &Vl[vrow * 72 + (2 * np + 1) * 16 + vcol]);
            float* o0 = oreg[4 * np + 0];
            float* o1 = oreg[4 * np + 1];
            float* o2 = oreg[4 * np + 2];
            float* o3 = oreg[4 * np + 3];
            // term hh
            MMA_BF16(o0, pah, (vhA + 0)); MMA_BF16(o1, pah, (vhA + 2));
            MMA_BF16(o2, pah, (vhB + 0)); MMA_BF16(o3, pah, (vhB + 2));
            // term hl
            MMA_BF16(o0, pah, (vlA + 0)); MMA_BF16(o1, pah, (vlA + 2));
            MMA_BF16(o2, pah, (vlB + 0)); MMA_BF16(o3, pah, (vlB + 2));
            // term lh
            MMA_BF16(o0, pal, (vhA + 0)); MMA_BF16(o1, pal, (vhA + 2));
            MMA_BF16(o2, pal, (vhB + 0)); MMA_BF16(o3, pal, (vhB + 2));
        }
    }

    __syncthreads();
    int r = lane >> 2, cc = (lane & 3) * 2;
#pragma unroll
    for (int nd = 0; nd < 8; nd++) {
        Ost[(r0 + r) * 65 + nd * 8 + cc]         = oreg[nd][0] * inv0;
        Ost[(r0 + r) * 65 + nd * 8 + cc + 1]     = oreg[nd][1] * inv0;
        Ost[(r0 + r + 8) * 65 + nd * 8 + cc]     = oreg[nd][2] * inv1;
        Ost[(r0 + r + 8) * 65 + nd * 8 + cc + 1] = oreg[nd][3] * inv1;
    }
    __syncthreads();

    unsigned* op = g_o + ((long)(s * 16 + b) * 512 + h * 64) * 1024 + qt * 128;
    int plane = lane * 4;
    for (int dd = w; dd < 64; dd += 8) {
        uint4 t;
        t.x = pack_pair(Ost[(plane + 0) * 65 + dd]);
        t.y = pack_pair(Ost[(plane + 1) * 65 + dd]);
        t.z = pack_pair(Ost[(plane + 2) * 65 + dd]);
        t.w = pack_pair(Ost[(plane + 3) * 65 + dd]);
        *(uint4*)&op[(long)dd * 1024 + plane] = t;
    }
}

// ---------------------------------------------------------------------------
// Orchestration (attn stays at launch index 5 for the fixed ncu window).
// ---------------------------------------------------------------------------
extern "C" void kernel_launch(void* const* d_in, const int* in_sizes, int n_in,
                              void* d_out, int out_size)
{
    (void)in_sizes; (void)n_in; (void)out_size;
    #define F(i) ((const float*)d_in[i])

    cudaFuncSetAttribute(mma_gemm, cudaFuncAttributeMaxDynamicSharedMemorySize, GEMM_SMEM);
    cudaFuncSetAttribute(attn_kernel, cudaFuncAttributeMaxDynamicSharedMemorySize, ATT_SMEM);

    // 0: weight splits
    split_all_kernel<<<4096, 256>>>(F(7), F(19), F(13), F(25), F(26), F(28));

    // 1-2: depthwise convs
    int tot1 = 16 * 256 * 1024;
    int tot2 = 16 * 256 * 256;
    dwconv2_kernel<<<dim3((tot1 + 255) / 256, 2), 256>>>(
        F(0), F(1), F(2), F(3), F(4), F(5), F(6),
        F(14), F(15), F(16), F(17), F(18), 0, 1, 32);
    dwconv2_kernel<<<dim3((tot2 + 255) / 256, 2), 256>>>(
        F(0), F(1), F(8), F(9), F(10), F(11), F(12),
        F(20), F(21), F(22), F(23), F(24), 1, 2, 16);

    // 3: q projection  [512,1024]
    mma_gemm<<<dim3(1024 / BN, 512 / BM, 32), 256, GEMM_SMEM>>>(512, 1024, 256, 0, nullptr, nullptr, nullptr);
    // 4: kv projection [1024,256]
    mma_gemm<<<dim3(256 / BN, 1024 / BM, 32), 256, GEMM_SMEM>>>(1024, 256, 256, 1, nullptr, nullptr, nullptr);

    // 5: attention
    attn_kernel<<<2048, 256, ATT_SMEM>>>();

    // 6: out projection [256,1024]
    mma_gemm<<<dim3(1024 / BN, 256 / BM, 32), 256, GEMM_SMEM>>>(256, 1024, 512, 2, (float*)d_out, F(27), F(29));

    #undef F
}

// round 13
// speedup vs baseline: 1.2734x; 1.2734x over previous
#include <cuda_runtime.h>
#include <cuda_bf16.h>
#include <stdint.h>
#include <math.h>

// ---------------------------------------------------------------------------
// ConvCrossAttention, mma.sync bf16 with 3xBF16 hi/lo split (tcgen05 is not
// supported by the harness compile target). R13: attention restructured as
// 2-chunk online-softmax to halve smem (110.6KB) -> 2 CTAs/SM (16 warps).
// ---------------------------------------------------------------------------

__device__ unsigned g_yq [2*16*256*1024];  // dwconv q path  [s][b][c][p]
__device__ unsigned g_ykv[2*16*256*256];   // dwconv kv path [s][b][c][j]
__device__ unsigned g_q  [2*16*8*1024*64]; // [s][b][h][p][d]   (scale folded)
__device__ unsigned g_k  [2*16*8*256*64];
__device__ unsigned g_v  [2*16*8*256*64];
__device__ unsigned g_o  [2*16*512*1024];  // attn out [s][b][c=h*64+d][p]
__device__ __nv_bfloat16 g_wq_hi [2*512*256],  g_wq_lo [2*512*256];
__device__ __nv_bfloat16 g_wkv_hi[2*1024*256], g_wkv_lo[2*1024*256];
__device__ __nv_bfloat16 g_wo_hi [2*256*512],  g_wo_lo [2*256*512];

__device__ __forceinline__ unsigned pack_pair(float v)
{
    __nv_bfloat162 p;
    p.x = __float2bfloat16(v);
    p.y = __float2bfloat16(v - __bfloat162float(p.x));
    return *(unsigned*)&p;
}

__device__ __forceinline__ void pack2(float a, float b, unsigned& hi, unsigned& lo)
{
    __nv_bfloat162 h = __floats2bfloat162_rn(a, b);
    __nv_bfloat162 l = __floats2bfloat162_rn(a - __bfloat162float(h.x),
                                             b - __bfloat162float(h.y));
    hi = *(unsigned*)&h;
    lo = *(unsigned*)&l;
}

// ---------------------------------------------------------------------------
__global__ void split_all_kernel(const float* __restrict__ wq0, const float* __restrict__ wq1,
                                 const float* __restrict__ wkv0, const float* __restrict__ wkv1,
                                 const float* __restrict__ wo0, const float* __restrict__ wo1)
{
    int i = blockIdx.x * blockDim.x + threadIdx.x;
    const float* src;
    __nv_bfloat16 *hi, *lo;
    int dst;
    float scale = 1.0f;
    if (i < 262144) {
        src = (i >= 131072) ? wq1 + (i - 131072) : wq0 + i;
        hi = g_wq_hi; lo = g_wq_lo; dst = i; scale = 0.125f;
    } else if (i < 786432) {
        int j = i - 262144;
        src = (j >= 262144) ? wkv1 + (j - 262144) : wkv0 + j;
        hi = g_wkv_hi; lo = g_wkv_lo; dst = j;
    } else {
        int j = i - 786432;
        src = (j >= 131072) ? wo1 + (j - 131072) : wo0 + j;
        hi = g_wo_hi; lo = g_wo_lo; dst = j;
    }
    float v = *src * scale;
    __nv_bfloat16 h = __float2bfloat16(v);
    hi[dst] = h;
    lo[dst] = __float2bfloat16(v - __bfloat162float(h));
}

// ---------------------------------------------------------------------------
__global__ void dwconv2_kernel(const float* __restrict__ x0, const float* __restrict__ x1,
                               const float* __restrict__ dw0, const float* __restrict__ g0,
                               const float* __restrict__ b0, const float* __restrict__ rm0,
                               const float* __restrict__ rv0,
                               const float* __restrict__ dw1, const float* __restrict__ g1,
                               const float* __restrict__ b1, const float* __restrict__ rm1,
                               const float* __restrict__ rv1,
                               int dst_kv, int stride, int OH)
{
    int idx = blockIdx.x * blockDim.x + threadIdx.x;
    int total = 16 * 256 * OH * OH;
    if (idx >= total) return;
    int sp = blockIdx.y;
    const float* x  = sp ? x1 : x0;
    const float* dw = sp ? dw1 : dw0;
    const float* gam = sp ? g1 : g0;
    const float* bet = sp ? b1 : b0;
    const float* rm = sp ? rm1 : rm0;
    const float* rv = sp ? rv1 : rv0;

    int ox = idx % OH; int t = idx / OH;
    int oy = t % OH;   t /= OH;
    int c = t & 255;   int b = t >> 8;

    const float* xp = x + ((b << 8) | c) * 1024;
    const float* w  = dw + c * 9;
    int iy0 = oy * stride - 1, ix0 = ox * stride - 1;
    float acc = 0.f;
#pragma unroll
    for (int ky = 0; ky < 3; ky++) {
        int iy = iy0 + ky;
        if ((unsigned)iy < 32u) {
#pragma unroll
            for (int kx = 0; kx < 3; kx++) {
                int ix = ix0 + kx;
                if ((unsigned)ix < 32u) acc += xp[iy * 32 + ix] * w[ky * 3 + kx];
            }
        }
    }
    float inv = gam[c] * rsqrtf(rv[c] + 1e-5f);
    float r = acc * inv + (bet[c] - rm[c] * inv);
    unsigned* y = dst_kv ? g_ykv : g_yq;
    y[sp * total + idx] = pack_pair(r);
}

// ---------------------------------------------------------------------------
// MMA primitives
// ---------------------------------------------------------------------------
#define MMA_BF16(d, a, b) asm volatile( \
    "mma.sync.aligned.m16n8k16.row.col.f32.bf16.bf16.f32 " \
    "{%0,%1,%2,%3}, {%4,%5,%6,%7}, {%8,%9}, {%0,%1,%2,%3};" \
    : "+f"(d[0]), "+f"(d[1]), "+f"(d[2]), "+f"(d[3]) \
    : "r"(a[0]), "r"(a[1]), "r"(a[2]), "r"(a[3]), "r"(b[0]), "r"(b[1]))

#define LDSM_X4(R, p) { unsigned _ad = (unsigned)__cvta_generic_to_shared(p); \
    asm volatile("ldmatrix.sync.aligned.m8n8.x4.shared.b16 {%0,%1,%2,%3}, [%4];" \
        : "=r"(R[0]), "=r"(R[1]), "=r"(R[2]), "=r"(R[3]) : "r"(_ad)); }

#define LDSM_X4T(R, p) { unsigned _ad = (unsigned)__cvta_generic_to_shared(p); \
    asm volatile("ldmatrix.sync.aligned.m8n8.x4.trans.shared.b16 {%0,%1,%2,%3}, [%4];" \
        : "=r"(R[0]), "=r"(R[1]), "=r"(R[2]), "=r"(R[3]) : "r"(_ad)); }

#define CP_ASYNC16(smem_u32, gptr) \
    asm volatile("cp.async.cg.shared.global [%0], [%1], 16;" :: "r"(smem_u32), "l"(gptr))
#define CP_COMMIT() asm volatile("cp.async.commit_group;")
#define CP_WAIT0()  asm volatile("cp.async.wait_group 0;")

// ---------------------------------------------------------------------------
// Pipelined tensor-core GEMM (3xBF16 split), unchanged from best (R11).
// ---------------------------------------------------------------------------
#define BM 128
#define BN 128
#define BK 32
#define SA_STR 40
#define SB_STR 136
#define A_PLANE 10240
#define B_PLANE 8704
#define BUF_BYTES 37888
#define GEMM_SMEM 75776

__global__ __launch_bounds__(256) void mma_gemm(int M, int N, int K, int mode,
                                                float* __restrict__ Ob,
                                                const float* __restrict__ bias0,
                                                const float* __restrict__ bias1)
{
    extern __shared__ char gsm[];
    unsigned* sC = (unsigned*)gsm;

    int z = blockIdx.z, s = z >> 4;
    const __nv_bfloat16 *Ah, *Al;
    const unsigned* Bp;
    if (mode == 0) {
        Ah = g_wq_hi  + s * 512 * 256;  Al = g_wq_lo  + s * 512 * 256;
        Bp = g_yq  + (long)z * 256 * 1024;
    } else if (mode == 1) {
        Ah = g_wkv_hi + s * 1024 * 256; Al = g_wkv_lo + s * 1024 * 256;
        Bp = g_ykv + (long)z * 256 * 256;
    } else {
        Ah = g_wo_hi  + s * 256 * 512;  Al = g_wo_lo  + s * 256 * 512;
        Bp = g_o   + (long)z * 512 * 1024;
    }

    int m0 = blockIdx.y * BM, n0 = blockIdx.x * BN;
    int tid = threadIdx.x, lane = tid & 31, wid = tid >> 5;
    int wm = wid >> 2, wn = wid & 3;

    float acc[4][4][4] = {};

    int arow = tid >> 2, acol = (tid & 3) * 8;
    int lr = lane & 15, lc = (lane >> 4) * 8;
    int brow2 = (lane & 7) + ((lane >> 3) & 1) * 8;
    int bcol2 = (lane >> 4) * 8;

    __nv_bfloat16* pAh[2] = {(__nv_bfloat16*)gsm, (__nv_bfloat16*)(gsm + BUF_BYTES)};
    __nv_bfloat16* pAl[2] = {(__nv_bfloat16*)(gsm + A_PLANE), (__nv_bfloat16*)(gsm + BUF_BYTES + A_PLANE)};
    __nv_bfloat16* pBh[2] = {(__nv_bfloat16*)(gsm + 2*A_PLANE), (__nv_bfloat16*)(gsm + BUF_BYTES + 2*A_PLANE)};
    __nv_bfloat16* pBl[2] = {(__nv_bfloat16*)(gsm + 2*A_PLANE + B_PLANE), (__nv_bfloat16*)(gsm + BUF_BYTES + 2*A_PLANE + B_PLANE)};

    uint4 stB[4];
    int nk = K / BK;

    int bR[2], bC[2];
#pragma unroll
    for (int j = 0; j < 2; j++) { int sj = tid + 256 * j; bR[j] = sj >> 4; bC[j] = (sj & 15) * 8; }

    {
#pragma unroll
        for (int r = 0; r < 2; r++) {
            unsigned d0 = (unsigned)__cvta_generic_to_shared(&pAh[0][(arow + 64 * r) * SA_STR + acol]);
            unsigned d1 = (unsigned)__cvta_generic_to_shared(&pAl[0][(arow + 64 * r) * SA_STR + acol]);
            CP_ASYNC16(d0, &Ah[(long)(m0 + arow + 64 * r) * K + acol]);
            CP_ASYNC16(d1, &Al[(long)(m0 + arow + 64 * r) * K + acol]);
        }
        CP_COMMIT();
#pragma unroll
        for (int j = 0; j < 2; j++) {
            const unsigned* src = &Bp[(long)bR[j] * N + n0 + bC[j]];
            stB[2 * j]     = *(const uint4*)src;
            stB[2 * j + 1] = *(const uint4*)(src + 4);
        }
#pragma unroll
        for (int j = 0; j < 2; j++) {
            uint4 u0 = stB[2 * j], u1 = stB[2 * j + 1];
            uint4 hv = make_uint4(__byte_perm(u0.x, u0.y, 0x5410), __byte_perm(u0.z, u0.w, 0x5410),
                                  __byte_perm(u1.x, u1.y, 0x5410), __byte_perm(u1.z, u1.w, 0x5410));
            uint4 lv = make_uint4(__byte_perm(u0.x, u0.y, 0x7632), __byte_perm(u0.z, u0.w, 0x7632),
                                  __byte_perm(u1.x, u1.y, 0x7632), __byte_perm(u1.z, u1.w, 0x7632));
            *(uint4*)&pBh[0][bR[j] * SB_STR + bC[j]] = hv;
            *(uint4*)&pBl[0][bR[j] * SB_STR + bC[j]] = lv;
        }
        CP_WAIT0();
        __syncthreads();
    }

    for (int i = 0; i < nk; i++) {
        int cur = i & 1, nxt = cur ^ 1;
        bool has_next = (i + 1 < nk);
        if (has_next) {
            int k0 = (i + 1) * BK;
#pragma unroll
            for (int r = 0; r < 2; r++) {
                unsigned d0 = (unsigned)__cvta_generic_to_shared(&pAh[nxt][(arow + 64 * r) * SA_STR + acol]);
                unsigned d1 = (unsigned)__cvta_generic_to_shared(&pAl[nxt][(arow + 64 * r) * SA_STR + acol]);
                CP_ASYNC16(d0, &Ah[(long)(m0 + arow + 64 * r) * K + k0 + acol]);
                CP_ASYNC16(d1, &Al[(long)(m0 + arow + 64 * r) * K + k0 + acol]);
            }
            CP_COMMIT();
#pragma unroll
            for (int j = 0; j < 2; j++) {
                const unsigned* src = &Bp[(long)(k0 + bR[j]) * N + n0 + bC[j]];
                stB[2 * j]     = *(const uint4*)src;
                stB[2 * j + 1] = *(const uint4*)(src + 4);
            }
        }

#pragma unroll
        for (int kk = 0; kk < BK; kk += 16) {
            unsigned ah[4][4], al[4][4], bh4[2][4], bl4[2][4];
#pragma unroll
            for (int mi = 0; mi < 4; mi++) {
                LDSM_X4(ah[mi], &pAh[cur][(wm * 64 + mi * 16 + lr) * SA_STR + kk + lc]);
                LDSM_X4(al[mi], &pAl[cur][(wm * 64 + mi * 16 + lr) * SA_STR + kk + lc]);
            }
#pragma unroll
            for (int ni2 = 0; ni2 < 2; ni2++) {
                LDSM_X4T(bh4[ni2], &pBh[cur][(kk + brow2) * SB_STR + wn * 32 + ni2 * 16 + bcol2]);
                LDSM_X4T(bl4[ni2], &pBl[cur][(kk + brow2) * SB_STR + wn * 32 + ni2 * 16 + bcol2]);
            }
#pragma unroll
            for (int mi = 0; mi < 4; mi++)
#pragma unroll
                for (int ni = 0; ni < 4; ni++) {
                    unsigned* bh = bh4[ni >> 1] + (ni & 1) * 2;
                    MMA_BF16(acc[mi][ni], ah[mi], bh);
                }
#pragma unroll
            for (int mi = 0; mi < 4; mi++)
#pragma unroll
                for (int ni = 0; ni < 4; ni++) {
                    unsigned* bl = bl4[ni >> 1] + (ni & 1) * 2;
                    MMA_BF16(acc[mi][ni], ah[mi], bl);
                }
#pragma unroll
            for (int mi = 0; mi < 4; mi++)
#pragma unroll
                for (int ni = 0; ni < 4; ni++) {
                    unsigned* bh = bh4[ni >> 1] + (ni & 1) * 2;
                    MMA_BF16(acc[mi][ni], al[mi], bh);
                }
        }

        if (has_next) {
#pragma unroll
            for (int j = 0; j < 2; j++) {
                uint4 u0 = stB[2 * j], u1 = stB[2 * j + 1];
                uint4 hv = make_uint4(__byte_perm(u0.x, u0.y, 0x5410), __byte_perm(u0.z, u0.w, 0x5410),
                                      __byte_perm(u1.x, u1.y, 0x5410), __byte_perm(u1.z, u1.w, 0x5410));
                uint4 lv = make_uint4(__byte_perm(u0.x, u0.y, 0x7632), __byte_perm(u0.z, u0.w, 0x7632),
                                      __byte_perm(u1.x, u1.y, 0x7632), __byte_perm(u1.z, u1.w, 0x7632));
                *(uint4*)&pBh[nxt][bR[j] * SB_STR + bC[j]] = hv;
                *(uint4*)&pBl[nxt][bR[j] * SB_STR + bC[j]] = lv;
            }
            CP_WAIT0();
        }
        __syncthreads();
    }

    int r = lane >> 2, cc = (lane & 3) * 2;
    if (mode == 2) {
        const float* bias = s ? bias1 : bias0;
#pragma unroll
        for (int mi = 0; mi < 4; mi++)
#pragma unroll
            for (int ni = 0; ni < 4; ni++)
#pragma unroll
                for (int half = 0; half < 2; half++) {
                    int m = m0 + wm * 64 + mi * 16 + r + half * 8;
                    int n = n0 + wn * 32 + ni * 8 + cc;
                    float bv = bias[m];
                    float2 v = make_float2(acc[mi][ni][half * 2] + bv,
                                           acc[mi][ni][half * 2 + 1] + bv);
                    *(float2*)&Ob[((long)z * M + m) * N + n] = v;
                }
    } else {
#pragma unroll
        for (int mi = 0; mi < 4; mi++)
#pragma unroll
            for (int ni = 0; ni < 4; ni++)
#pragma unroll
                for (int half = 0; half < 2; half++) {
                    int ml = wm * 64 + mi * 16 + r + half * 8;
                    int nl = wn * 32 + ni * 8 + cc;
                    sC[ml * 129 + nl]     = pack_pair(acc[mi][ni][half * 2]);
                    sC[ml * 129 + nl + 1] = pack_pair(acc[mi][ni][half * 2 + 1]);
                }
        __syncthreads();

        int n = tid & 127, hh = tid >> 7;
        int mrow = m0 + hh * 64;
        unsigned* dst;
        long base;
        if (mode == 0) {
            dst = g_q;
            base = ((long)(z * 8 + (mrow >> 6)) * 1024 + n0 + n) * 64;
        } else if (mrow < 512) {
            dst = g_k;
            base = ((long)(z * 8 + (mrow >> 6)) * 256 + n0 + n) * 64;
        } else {
            dst = g_v;
            base = ((long)(z * 8 + ((mrow - 512) >> 6)) * 256 + n0 + n) * 64;
        }
#pragma unroll
        for (int d4 = 0; d4 < 64; d4 += 4) {
            uint4 t;
            t.x = sC[(hh * 64 + d4 + 0) * 129 + n];
            t.y = sC[(hh * 64 + d4 + 1) * 129 + n];
            t.z = sC[(hh * 64 + d4 + 2) * 129 + n];
            t.w = sC[(hh * 64 + d4 + 3) * 129 + n];
            *(uint4*)&dst[base + d4] = t;
        }
    }
}

// ---------------------------------------------------------------------------
// Cross attention v2: 2 KV chunks of 128 + online softmax. smem 110.6KB ->
// 2 CTAs/SM (16 warps). One CTA per (s,b,h,qt).
// ---------------------------------------------------------------------------
#define ATT_SMEM 110592

__global__ __launch_bounds__(256, 2) void attn_kernel()
{
    extern __shared__ char smx[];
    __nv_bfloat16* Qh = (__nv_bfloat16*)(smx);            // 128*72*2 = 18432
    __nv_bfloat16* Ql = (__nv_bfloat16*)(smx + 18432);
    __nv_bfloat16* Kh = (__nv_bfloat16*)(smx + 36864);    // chunk: 128 rows
    __nv_bfloat16* Kl = (__nv_bfloat16*)(smx + 55296);
    __nv_bfloat16* Vh = (__nv_bfloat16*)(smx + 73728);
    __nv_bfloat16* Vl = (__nv_bfloat16*)(smx + 92160);
    float*        Ost = (float*)smx;                      // overlays Q at end

    int bid = blockIdx.x;
    int qt = bid & 7, bhs = bid >> 3;
    int s = bhs >> 7, bh = bhs & 127, h = bh & 7, b = bh >> 3;

    const unsigned* qp = g_q + ((long)(s * 128 + bh) * 1024 + qt * 128) * 64;
    const unsigned* kp = g_k + (long)((1 - s) * 128 + bh) * 256 * 64;
    const unsigned* vp = g_v + (long)((1 - s) * 128 + bh) * 256 * 64;

    int tid = threadIdx.x, lane = tid & 31, w = tid >> 5;
    int r0 = w * 16;
    int krow = (lane & 7) + ((lane >> 4) << 3);

    // load Q (128 rows of 64 pairs), de-interleave
    for (int c = tid; c < 2048; c += 256) {
        int row = c >> 4, seg = (c & 15) * 4;
        uint4 u = *(const uint4*)&qp[row * 64 + seg];
        *(uint2*)&Qh[row * 72 + seg] = make_uint2(__byte_perm(u.x, u.y, 0x5410), __byte_perm(u.z, u.w, 0x5410));
        *(uint2*)&Ql[row * 72 + seg] = make_uint2(__byte_perm(u.x, u.y, 0x7632), __byte_perm(u.z, u.w, 0x7632));
    }

    float oreg[8][4] = {};
    float mrow0 = -1e30f, mrow1 = -1e30f, sum0 = 0.f, sum1 = 0.f;

    for (int ch = 0; ch < 2; ch++) {
        if (ch) __syncthreads();   // all warps done with prev chunk's K,V

        // load K,V chunk (128 rows)
        for (int c = tid; c < 2048; c += 256) {
            int row = c >> 4, seg = (c & 15) * 4;
            uint4 u = *(const uint4*)&kp[(ch * 128 + row) * 64 + seg];
            *(uint2*)&Kh[row * 72 + seg] = make_uint2(__byte_perm(u.x, u.y, 0x5410), __byte_perm(u.z, u.w, 0x5410));
            *(uint2*)&Kl[row * 72 + seg] = make_uint2(__byte_perm(u.x, u.y, 0x7632), __byte_perm(u.z, u.w, 0x7632));
            u = *(const uint4*)&vp[(ch * 128 + row) * 64 + seg];
            *(uint2*)&Vh[row * 72 + seg] = make_uint2(__byte_perm(u.x, u.y, 0x5410), __byte_perm(u.z, u.w, 0x5410));
            *(uint2*)&Vl[row * 72 + seg] = make_uint2(__byte_perm(u.x, u.y, 0x7632), __byte_perm(u.z, u.w, 0x7632));
        }
        __syncthreads();

        // ---- S chunk = Q @ Kc^T : sreg[16][4], paired tiles + term-major
        float sreg[16][4];
#pragma unroll
        for (int nt = 0; nt < 16; nt++) {
            sreg[nt][0] = 0.f; sreg[nt][1] = 0.f; sreg[nt][2] = 0.f; sreg[nt][3] = 0.f;
        }
        for (int kk = 0; kk < 4; kk++) {
            unsigned ah[4], al[4];
            int qoff = (r0 + (lane & 15)) * 72 + kk * 16 + (lane >> 4) * 8;
            LDSM_X4(ah, &Qh[qoff]);
            LDSM_X4(al, &Ql[qoff]);
            int koff = kk * 16 + ((lane >> 3) & 1) * 8;
#pragma unroll
            for (int nt4 = 0; nt4 < 4; nt4++) {
                unsigned khA[4], klA[4], khB[4], klB[4];
                LDSM_X4(khA, &Kh[((2 * nt4) * 16 + krow) * 72 + koff]);
                LDSM_X4(klA, &Kl[((2 * nt4) * 16 + krow) * 72 + koff]);
                LDSM_X4(khB, &Kh[((2 * nt4 + 1) * 16 + krow) * 72 + koff]);
                LDSM_X4(klB, &Kl[((2 * nt4 + 1) * 16 + krow) * 72 + koff]);
                float* s0 = sreg[4 * nt4 + 0];
                float* s1 = sreg[4 * nt4 + 1];
                float* s2 = sreg[4 * nt4 + 2];
                float* s3 = sreg[4 * nt4 + 3];
                MMA_BF16(s0, ah, (khA + 0)); MMA_BF16(s1, ah, (khA + 2));
                MMA_BF16(s2, ah, (khB + 0)); MMA_BF16(s3, ah, (khB + 2));
                MMA_BF16(s0, ah, (klA + 0)); MMA_BF16(s1, ah, (klA + 2));
                MMA_BF16(s2, ah, (klB + 0)); MMA_BF16(s3, ah, (klB + 2));
                MMA_BF16(s0, al, (khA + 0)); MMA_BF16(s1, al, (khA + 2));
                MMA_BF16(s2, al, (khB + 0)); MMA_BF16(s3, al, (khB + 2));
            }
        }

        // ---- online softmax update (rows r=lane>>2 and r+8)
        {
            float mc0 = -1e30f, mc1 = -1e30f;
#pragma unroll
            for (int nt = 0; nt < 16; nt++) {
                mc0 = fmaxf(mc0, fmaxf(sreg[nt][0], sreg[nt][1]));
                mc1 = fmaxf(mc1, fmaxf(sreg[nt][2], sreg[nt][3]));
            }
            mc0 = fmaxf(mc0, __shfl_xor_sync(0xffffffffu, mc0, 1));
            mc0 = fmaxf(mc0, __shfl_xor_sync(0xffffffffu, mc0, 2));
            mc1 = fmaxf(mc1, __shfl_xor_sync(0xffffffffu, mc1, 1));
            mc1 = fmaxf(mc1, __shfl_xor_sync(0xffffffffu, mc1, 2));
            float mn0 = fmaxf(mrow0, mc0), mn1 = fmaxf(mrow1, mc1);
            float f0 = __expf(mrow0 - mn0), f1 = __expf(mrow1 - mn1);
            mrow0 = mn0; mrow1 = mn1;

            float cs0 = 0.f, cs1 = 0.f;
#pragma unroll
            for (int nt = 0; nt < 16; nt++) {
                float e0 = __expf(sreg[nt][0] - mn0); sreg[nt][0] = e0; cs0 += e0;
                float e1 = __expf(sreg[nt][1] - mn0); sreg[nt][1] = e1; cs0 += e1;
                float e2 = __expf(sreg[nt][2] - mn1); sreg[nt][2] = e2; cs1 += e2;
                float e3 = __expf(sreg[nt][3] - mn1); sreg[nt][3] = e3; cs1 += e3;
            }
            cs0 += __shfl_xor_sync(0xffffffffu, cs0, 1);
            cs0 += __shfl_xor_sync(0xffffffffu, cs0, 2);
            cs1 += __shfl_xor_sync(0xffffffffu, cs1, 1);
            cs1 += __shfl_xor_sync(0xffffffffu, cs1, 2);
            sum0 = sum0 * f0 + cs0;
            sum1 = sum1 * f1 + cs1;
#pragma unroll
            for (int nd = 0; nd < 8; nd++) {
                oreg[nd][0] *= f0; oreg[nd][1] *= f0;
                oreg[nd][2] *= f1; oreg[nd][3] *= f1;
            }
        }

        // ---- O += Pc @ Vc : paired d-tiles, term-major
#pragma unroll
        for (int kt = 0; kt < 8; kt++) {
            unsigned pah[4], pal[4];
            pack2(sreg[2 * kt][0],     sreg[2 * kt][1],     pah[0], pal[0]);
            pack2(sreg[2 * kt][2],     sreg[2 * kt][3],     pah[1], pal[1]);
            pack2(sreg[2 * kt + 1][0], sreg[2 * kt + 1][1], pah[2], pal[2]);
            pack2(sreg[2 * kt + 1][2], sreg[2 * kt + 1][3], pah[3], pal[3]);
            int vrow = kt * 16 + (lane & 7) + ((lane >> 3) & 1) * 8;
            int vcol = (lane >> 4) << 3;
#pragma unroll
            for (int np = 0; np < 2; np++) {
                unsigned vhA[4], vlA[4], vhB[4], vlB[4];
                LDSM_X4T(vhA, &Vh[vrow * 72 + (2 * np) * 16 + vcol]);
                LDSM_X4T(vlA, &Vl[vrow * 72 + (2 * np) * 16 + vcol]);
                LDSM_X4T(vhB, &Vh[vrow * 72 + (2 * np + 1) * 16 + vcol]);
                LDSM_X4T(vlB, &Vl[vrow * 72 + (2 * np + 1) * 16 + vcol]);
                float* o0 = oreg[4 * np + 0];
                float* o1 = oreg[4 * np + 1];
                float* o2 = oreg[4 * np + 2];
                float* o3 = oreg[4 * np + 3];
                MMA_BF16(o0, pah, (vhA + 0)); MMA_BF16(o1, pah, (vhA + 2));
                MMA_BF16(o2, pah, (vhB + 0)); MMA_BF16(o3, pah, (vhB + 2));
                MMA_BF16(o0, pah, (vlA + 0)); MMA_BF16(o1, pah, (vlA + 2));
                MMA_BF16(o2, pah, (vlB + 0)); MMA_BF16(o3, pah, (vlB + 2));
                MMA_BF16(o0, pal, (vhA + 0)); MMA_BF16(o1, pal, (vhA + 2));
                MMA_BF16(o2, pal, (vhB + 0)); MMA_BF16(o3, pal, (vhB + 2));
            }
        }
    }

    // ---- normalize, stage (Ost overlays Q), transposed coalesced write
    float inv0 = 1.f / sum0, inv1 = 1.f / sum1;
    __syncthreads();
    int r = lane >> 2, cc = (lane & 3) * 2;
#pragma unroll
    for (int nd = 0; nd < 8; nd++) {
        Ost[(r0 + r) * 65 + nd * 8 + cc]         = oreg[nd][0] * inv0;
        Ost[(r0 + r) * 65 + nd * 8 + cc + 1]     = oreg[nd][1] * inv0;
        Ost[(r0 + r + 8) * 65 + nd * 8 + cc]     = oreg[nd][2] * inv1;
        Ost[(r0 + r + 8) * 65 + nd * 8 + cc + 1] = oreg[nd][3] * inv1;
    }
    __syncthreads();

    unsigned* op = g_o + ((long)(s * 16 + b) * 512 + h * 64) * 1024 + qt * 128;
    int plane = lane * 4;
    for (int dd = w; dd < 64; dd += 8) {
        uint4 t;
        t.x = pack_pair(Ost[(plane + 0) * 65 + dd]);
        t.y = pack_pair(Ost[(plane + 1) * 65 + dd]);
        t.z = pack_pair(Ost[(plane + 2) * 65 + dd]);
        t.w = pack_pair(Ost[(plane + 3) * 65 + dd]);
        *(uint4*)&op[(long)dd * 1024 + plane] = t;
    }
}

// ---------------------------------------------------------------------------
// Orchestration.
// ---------------------------------------------------------------------------
extern "C" void kernel_launch(void* const* d_in, const int* in_sizes, int n_in,
                              void* d_out, int out_size)
{
    (void)in_sizes; (void)n_in; (void)out_size;
    #define F(i) ((const float*)d_in[i])

    cudaFuncSetAttribute(mma_gemm, cudaFuncAttributeMaxDynamicSharedMemorySize, GEMM_SMEM);
    cudaFuncSetAttribute(attn_kernel, cudaFuncAttributeMaxDynamicSharedMemorySize, ATT_SMEM);

    split_all_kernel<<<4096, 256>>>(F(7), F(19), F(13), F(25), F(26), F(28));

    int tot1 = 16 * 256 * 1024;
    int tot2 = 16 * 256 * 256;
    dwconv2_kernel<<<dim3((tot1 + 255) / 256, 2), 256>>>(
        F(0), F(1), F(2), F(3), F(4), F(5), F(6),
        F(14), F(15), F(16), F(17), F(18), 0, 1, 32);
    dwconv2_kernel<<<dim3((tot2 + 255) / 256, 2), 256>>>(
        F(0), F(1), F(8), F(9), F(10), F(11), F(12),
        F(20), F(21), F(22), F(23), F(24), 1, 2, 16);

    // q projection  [512,1024]
    mma_gemm<<<dim3(1024 / BN, 512 / BM, 32), 256, GEMM_SMEM>>>(512, 1024, 256, 0, nullptr, nullptr, nullptr);
    // kv projection [1024,256]
    mma_gemm<<<dim3(256 / BN, 1024 / BM, 32), 256, GEMM_SMEM>>>(1024, 256, 256, 1, nullptr, nullptr, nullptr);

    // attention
    attn_kernel<<<2048, 256, ATT_SMEM>>>();

    // out projection [256,1024]
    mma_gemm<<<dim3(1024 / BN, 256 / BM, 32), 256, GEMM_SMEM>>>(256, 1024, 512, 2, (float*)d_out, F(27), F(29));

    #undef F
}

// round 14
// speedup vs baseline: 1.3846x; 1.0874x over previous
#include <cuda_runtime.h>
#include <cuda_bf16.h>
#include <cuda_fp16.h>
#include <stdint.h>
#include <math.h>

// ---------------------------------------------------------------------------
// ConvCrossAttention. Projections: mma.sync bf16 3-term split (rel ~1e-5).
// Attention (R14): fp16 2-term — Q,P split hi/lo fp16; K,V single fp16.
// ---------------------------------------------------------------------------

__device__ unsigned g_yq [2*16*256*1024];  // dwconv q path  [s][b][c][p] bf16 pairs
__device__ unsigned g_ykv[2*16*256*256];   // dwconv kv path
__device__ unsigned g_q  [2*16*8*1024*64]; // fp16 pairs (hi|lo<<16), scale folded
__device__ __half   g_k  [2*16*8*256*64];  // single fp16
__device__ __half   g_v  [2*16*8*256*64];
__device__ unsigned g_o  [2*16*512*1024];  // attn out bf16 pairs [s][b][c][p]
__device__ __nv_bfloat16 g_wq_hi [2*512*256],  g_wq_lo [2*512*256];
__device__ __nv_bfloat16 g_wkv_hi[2*1024*256], g_wkv_lo[2*1024*256];
__device__ __nv_bfloat16 g_wo_hi [2*256*512],  g_wo_lo [2*256*512];

__device__ __forceinline__ unsigned pack_pair(float v)     // bf16 pair
{
    __nv_bfloat162 p;
    p.x = __float2bfloat16(v);
    p.y = __float2bfloat16(v - __bfloat162float(p.x));
    return *(unsigned*)&p;
}

__device__ __forceinline__ unsigned pack_pair_h(float v)   // fp16 pair
{
    __half2 p;
    p.x = __float2half(v);
    p.y = __float2half(v - __half2float(p.x));
    return *(unsigned*)&p;
}

__device__ __forceinline__ void pack2h(float a, float b, unsigned& hi, unsigned& lo)
{
    __half2 h = __floats2half2_rn(a, b);
    __half2 l = __floats2half2_rn(a - __half2float(h.x), b - __half2float(h.y));
    hi = *(unsigned*)&h;
    lo = *(unsigned*)&l;
}

// ---------------------------------------------------------------------------
__global__ void split_all_kernel(const float* __restrict__ wq0, const float* __restrict__ wq1,
                                 const float* __restrict__ wkv0, const float* __restrict__ wkv1,
                                 const float* __restrict__ wo0, const float* __restrict__ wo1)
{
    int i = blockIdx.x * blockDim.x + threadIdx.x;
    const float* src;
    __nv_bfloat16 *hi, *lo;
    int dst;
    float scale = 1.0f;
    if (i < 262144) {
        src = (i >= 131072) ? wq1 + (i - 131072) : wq0 + i;
        hi = g_wq_hi; lo = g_wq_lo; dst = i; scale = 0.125f;
    } else if (i < 786432) {
        int j = i - 262144;
        src = (j >= 262144) ? wkv1 + (j - 262144) : wkv0 + j;
        hi = g_wkv_hi; lo = g_wkv_lo; dst = j;
    } else {
        int j = i - 786432;
        src = (j >= 131072) ? wo1 + (j - 131072) : wo0 + j;
        hi = g_wo_hi; lo = g_wo_lo; dst = j;
    }
    float v = *src * scale;
    __nv_bfloat16 h = __float2bfloat16(v);
    hi[dst] = h;
    lo[dst] = __float2bfloat16(v - __bfloat162float(h));
}

// ---------------------------------------------------------------------------
__global__ void dwconv2_kernel(const float* __restrict__ x0, const float* __restrict__ x1,
                               const float* __restrict__ dw0, const float* __restrict__ g0,
                               const float* __restrict__ b0, const float* __restrict__ rm0,
                               const float* __restrict__ rv0,
                               const float* __restrict__ dw1, const float* __restrict__ g1,
                               const float* __restrict__ b1, const float* __restrict__ rm1,
                               const float* __restrict__ rv1,
                               int dst_kv, int stride, int OH)
{
    int idx = blockIdx.x * blockDim.x + threadIdx.x;
    int total = 16 * 256 * OH * OH;
    if (idx >= total) return;
    int sp = blockIdx.y;
    const float* x  = sp ? x1 : x0;
    const float* dw = sp ? dw1 : dw0;
    const float* gam = sp ? g1 : g0;
    const float* bet = sp ? b1 : b0;
    const float* rm = sp ? rm1 : rm0;
    const float* rv = sp ? rv1 : rv0;

    int ox = idx % OH; int t = idx / OH;
    int oy = t % OH;   t /= OH;
    int c = t & 255;   int b = t >> 8;

    const float* xp = x + ((b << 8) | c) * 1024;
    const float* w  = dw + c * 9;
    int iy0 = oy * stride - 1, ix0 = ox * stride - 1;
    float acc = 0.f;
#pragma unroll
    for (int ky = 0; ky < 3; ky++) {
        int iy = iy0 + ky;
        if ((unsigned)iy < 32u) {
#pragma unroll
            for (int kx = 0; kx < 3; kx++) {
                int ix = ix0 + kx;
                if ((unsigned)ix < 32u) acc += xp[iy * 32 + ix] * w[ky * 3 + kx];
            }
        }
    }
    float inv = gam[c] * rsqrtf(rv[c] + 1e-5f);
    float r = acc * inv + (bet[c] - rm[c] * inv);
    unsigned* y = dst_kv ? g_ykv : g_yq;
    y[sp * total + idx] = pack_pair(r);
}

// ---------------------------------------------------------------------------
// MMA primitives
// ---------------------------------------------------------------------------
#define MMA_BF16(d, a, b) asm volatile( \
    "mma.sync.aligned.m16n8k16.row.col.f32.bf16.bf16.f32 " \
    "{%0,%1,%2,%3}, {%4,%5,%6,%7}, {%8,%9}, {%0,%1,%2,%3};" \
    : "+f"(d[0]), "+f"(d[1]), "+f"(d[2]), "+f"(d[3]) \
    : "r"(a[0]), "r"(a[1]), "r"(a[2]), "r"(a[3]), "r"(b[0]), "r"(b[1]))

#define MMA_F16(d, a, b) asm volatile( \
    "mma.sync.aligned.m16n8k16.row.col.f32.f16.f16.f32 " \
    "{%0,%1,%2,%3}, {%4,%5,%6,%7}, {%8,%9}, {%0,%1,%2,%3};" \
    : "+f"(d[0]), "+f"(d[1]), "+f"(d[2]), "+f"(d[3]) \
    : "r"(a[0]), "r"(a[1]), "r"(a[2]), "r"(a[3]), "r"(b[0]), "r"(b[1]))

#define LDSM_X4(R, p) { unsigned _ad = (unsigned)__cvta_generic_to_shared(p); \
    asm volatile("ldmatrix.sync.aligned.m8n8.x4.shared.b16 {%0,%1,%2,%3}, [%4];" \
        : "=r"(R[0]), "=r"(R[1]), "=r"(R[2]), "=r"(R[3]) : "r"(_ad)); }

#define LDSM_X4T(R, p) { unsigned _ad = (unsigned)__cvta_generic_to_shared(p); \
    asm volatile("ldmatrix.sync.aligned.m8n8.x4.trans.shared.b16 {%0,%1,%2,%3}, [%4];" \
        : "=r"(R[0]), "=r"(R[1]), "=r"(R[2]), "=r"(R[3]) : "r"(_ad)); }

#define CP_ASYNC16(smem_u32, gptr) \
    asm volatile("cp.async.cg.shared.global [%0], [%1], 16;" :: "r"(smem_u32), "l"(gptr))
#define CP_COMMIT() asm volatile("cp.async.commit_group;")
#define CP_WAIT0()  asm volatile("cp.async.wait_group 0;")

// ---------------------------------------------------------------------------
// Pipelined bf16 3-term GEMM (projections + out proj), as in the 518us best.
// mode 0 -> g_q (fp16 pairs), mode 1 -> g_k/g_v (single fp16), mode 2 -> fp32.
// ---------------------------------------------------------------------------
#define BM 128
#define BN 128
#define BK 32
#define SA_STR 40
#define SB_STR 136
#define A_PLANE 10240
#define B_PLANE 8704
#define BUF_BYTES 37888
#define GEMM_SMEM 75776

__global__ __launch_bounds__(256) void mma_gemm(int M, int N, int K, int mode,
                                                float* __restrict__ Ob,
                                                const float* __restrict__ bias0,
                                                const float* __restrict__ bias1)
{
    extern __shared__ char gsm[];
    unsigned* sC = (unsigned*)gsm;

    int z = blockIdx.z, s = z >> 4;
    const __nv_bfloat16 *Ah, *Al;
    const unsigned* Bp;
    if (mode == 0) {
        Ah = g_wq_hi  + s * 512 * 256;  Al = g_wq_lo  + s * 512 * 256;
        Bp = g_yq  + (long)z * 256 * 1024;
    } else if (mode == 1) {
        Ah = g_wkv_hi + s * 1024 * 256; Al = g_wkv_lo + s * 1024 * 256;
        Bp = g_ykv + (long)z * 256 * 256;
    } else {
        Ah = g_wo_hi  + s * 256 * 512;  Al = g_wo_lo  + s * 256 * 512;
        Bp = g_o   + (long)z * 512 * 1024;
    }

    int m0 = blockIdx.y * BM, n0 = blockIdx.x * BN;
    int tid = threadIdx.x, lane = tid & 31, wid = tid >> 5;
    int wm = wid >> 2, wn = wid & 3;

    float acc[4][4][4] = {};

    int arow = tid >> 2, acol = (tid & 3) * 8;
    int lr = lane & 15, lc = (lane >> 4) * 8;
    int brow2 = (lane & 7) + ((lane >> 3) & 1) * 8;
    int bcol2 = (lane >> 4) * 8;

    __nv_bfloat16* pAh[2] = {(__nv_bfloat16*)gsm, (__nv_bfloat16*)(gsm + BUF_BYTES)};
    __nv_bfloat16* pAl[2] = {(__nv_bfloat16*)(gsm + A_PLANE), (__nv_bfloat16*)(gsm + BUF_BYTES + A_PLANE)};
    __nv_bfloat16* pBh[2] = {(__nv_bfloat16*)(gsm + 2*A_PLANE), (__nv_bfloat16*)(gsm + BUF_BYTES + 2*A_PLANE)};
    __nv_bfloat16* pBl[2] = {(__nv_bfloat16*)(gsm + 2*A_PLANE + B_PLANE), (__nv_bfloat16*)(gsm + BUF_BYTES + 2*A_PLANE + B_PLANE)};

    uint4 stB[4];
    int nk = K / BK;

    int bR[2], bC[2];
#pragma unroll
    for (int j = 0; j < 2; j++) { int sj = tid + 256 * j; bR[j] = sj >> 4; bC[j] = (sj & 15) * 8; }

    {
#pragma unroll
        for (int r = 0; r < 2; r++) {
            unsigned d0 = (unsigned)__cvta_generic_to_shared(&pAh[0][(arow + 64 * r) * SA_STR + acol]);
            unsigned d1 = (unsigned)__cvta_generic_to_shared(&pAl[0][(arow + 64 * r) * SA_STR + acol]);
            CP_ASYNC16(d0, &Ah[(long)(m0 + arow + 64 * r) * K + acol]);
            CP_ASYNC16(d1, &Al[(long)(m0 + arow + 64 * r) * K + acol]);
        }
        CP_COMMIT();
#pragma unroll
        for (int j = 0; j < 2; j++) {
            const unsigned* src = &Bp[(long)bR[j] * N + n0 + bC[j]];
            stB[2 * j]     = *(const uint4*)src;
            stB[2 * j + 1] = *(const uint4*)(src + 4);
        }
#pragma unroll
        for (int j = 0; j < 2; j++) {
            uint4 u0 = stB[2 * j], u1 = stB[2 * j + 1];
            uint4 hv = make_uint4(__byte_perm(u0.x, u0.y, 0x5410), __byte_perm(u0.z, u0.w, 0x5410),
                                  __byte_perm(u1.x, u1.y, 0x5410), __byte_perm(u1.z, u1.w, 0x5410));
            uint4 lv = make_uint4(__byte_perm(u0.x, u0.y, 0x7632), __byte_perm(u0.z, u0.w, 0x7632),
                                  __byte_perm(u1.x, u1.y, 0x7632), __byte_perm(u1.z, u1.w, 0x7632));
            *(uint4*)&pBh[0][bR[j] * SB_STR + bC[j]] = hv;
            *(uint4*)&pBl[0][bR[j] * SB_STR + bC[j]] = lv;
        }
        CP_WAIT0();
        __syncthreads();
    }

    for (int i = 0; i < nk; i++) {
        int cur = i & 1, nxt = cur ^ 1;
        bool has_next = (i + 1 < nk);
        if (has_next) {
            int k0 = (i + 1) * BK;
#pragma unroll
            for (int r = 0; r < 2; r++) {
                unsigned d0 = (unsigned)__cvta_generic_to_shared(&pAh[nxt][(arow + 64 * r) * SA_STR + acol]);
                unsigned d1 = (unsigned)__cvta_generic_to_shared(&pAl[nxt][(arow + 64 * r) * SA_STR + acol]);
                CP_ASYNC16(d0, &Ah[(long)(m0 + arow + 64 * r) * K + k0 + acol]);
                CP_ASYNC16(d1, &Al[(long)(m0 + arow + 64 * r) * K + k0 + acol]);
            }
            CP_COMMIT();
#pragma unroll
            for (int j = 0; j < 2; j++) {
                const unsigned* src = &Bp[(long)(k0 + bR[j]) * N + n0 + bC[j]];
                stB[2 * j]     = *(const uint4*)src;
                stB[2 * j + 1] = *(const uint4*)(src + 4);
            }
        }

#pragma unroll
        for (int kk = 0; kk < BK; kk += 16) {
            unsigned ah[4][4], al[4][4], bh4[2][4], bl4[2][4];
#pragma unroll
            for (int mi = 0; mi < 4; mi++) {
                LDSM_X4(ah[mi], &pAh[cur][(wm * 64 + mi * 16 + lr) * SA_STR + kk + lc]);
                LDSM_X4(al[mi], &pAl[cur][(wm * 64 + mi * 16 + lr) * SA_STR + kk + lc]);
            }
#pragma unroll
            for (int ni2 = 0; ni2 < 2; ni2++) {
                LDSM_X4T(bh4[ni2], &pBh[cur][(kk + brow2) * SB_STR + wn * 32 + ni2 * 16 + bcol2]);
                LDSM_X4T(bl4[ni2], &pBl[cur][(kk + brow2) * SB_STR + wn * 32 + ni2 * 16 + bcol2]);
            }
#pragma unroll
            for (int mi = 0; mi < 4; mi++)
#pragma unroll
                for (int ni = 0; ni < 4; ni++) {
                    unsigned* bh = bh4[ni >> 1] + (ni & 1) * 2;
                    MMA_BF16(acc[mi][ni], ah[mi], bh);
                }
#pragma unroll
            for (int mi = 0; mi < 4; mi++)
#pragma unroll
                for (int ni = 0; ni < 4; ni++) {
                    unsigned* bl = bl4[ni >> 1] + (ni & 1) * 2;
                    MMA_BF16(acc[mi][ni], ah[mi], bl);
                }
#pragma unroll
            for (int mi = 0; mi < 4; mi++)
#pragma unroll
                for (int ni = 0; ni < 4; ni++) {
                    unsigned* bh = bh4[ni >> 1] + (ni & 1) * 2;
                    MMA_BF16(acc[mi][ni], al[mi], bh);
                }
        }

        if (has_next) {
#pragma unroll
            for (int j = 0; j < 2; j++) {
                uint4 u0 = stB[2 * j], u1 = stB[2 * j + 1];
                uint4 hv = make_uint4(__byte_perm(u0.x, u0.y, 0x5410), __byte_perm(u0.z, u0.w, 0x5410),
                                      __byte_perm(u1.x, u1.y, 0x5410), __byte_perm(u1.z, u1.w, 0x5410));
                uint4 lv = make_uint4(__byte_perm(u0.x, u0.y, 0x7632), __byte_perm(u0.z, u0.w, 0x7632),
                                      __byte_perm(u1.x, u1.y, 0x7632), __byte_perm(u1.z, u1.w, 0x7632));
                *(uint4*)&pBh[nxt][bR[j] * SB_STR + bC[j]] = hv;
                *(uint4*)&pBl[nxt][bR[j] * SB_STR + bC[j]] = lv;
            }
            CP_WAIT0();
        }
        __syncthreads();
    }

    int r = lane >> 2, cc = (lane & 3) * 2;
    if (mode == 2) {
        const float* bias = s ? bias1 : bias0;
#pragma unroll
        for (int mi = 0; mi < 4; mi++)
#pragma unroll
            for (int ni = 0; ni < 4; ni++)
#pragma unroll
                for (int half = 0; half < 2; half++) {
                    int m = m0 + wm * 64 + mi * 16 + r + half * 8;
                    int n = n0 + wn * 32 + ni * 8 + cc;
                    float bv = bias[m];
                    float2 v = make_float2(acc[mi][ni][half * 2] + bv,
                                           acc[mi][ni][half * 2 + 1] + bv);
                    *(float2*)&Ob[((long)z * M + m) * N + n] = v;
                }
    } else {
#pragma unroll
        for (int mi = 0; mi < 4; mi++)
#pragma unroll
            for (int ni = 0; ni < 4; ni++)
#pragma unroll
                for (int half = 0; half < 2; half++) {
                    int ml = wm * 64 + mi * 16 + r + half * 8;
                    int nl = wn * 32 + ni * 8 + cc;
                    if (mode == 0) {
                        sC[ml * 129 + nl]     = pack_pair_h(acc[mi][ni][half * 2]);
                        sC[ml * 129 + nl + 1] = pack_pair_h(acc[mi][ni][half * 2 + 1]);
                    } else {
                        sC[ml * 129 + nl]     = (unsigned)__half_as_ushort(__float2half(acc[mi][ni][half * 2]));
                        sC[ml * 129 + nl + 1] = (unsigned)__half_as_ushort(__float2half(acc[mi][ni][half * 2 + 1]));
                    }
                }
        __syncthreads();

        int n = tid & 127, hh = tid >> 7;
        int mrow = m0 + hh * 64;
        if (mode == 0) {
            long base = ((long)(z * 8 + (mrow >> 6)) * 1024 + n0 + n) * 64;
#pragma unroll
            for (int d4 = 0; d4 < 64; d4 += 4) {
                uint4 t;
                t.x = sC[(hh * 64 + d4 + 0) * 129 + n];
                t.y = sC[(hh * 64 + d4 + 1) * 129 + n];
                t.z = sC[(hh * 64 + d4 + 2) * 129 + n];
                t.w = sC[(hh * 64 + d4 + 3) * 129 + n];
                *(uint4*)&g_q[base + d4] = t;
            }
        } else {
            __half* dsth;
            long base;
            if (mrow < 512) {
                dsth = g_k;
                base = ((long)(z * 8 + (mrow >> 6)) * 256 + n0 + n) * 64;
            } else {
                dsth = g_v;
                base = ((long)(z * 8 + ((mrow - 512) >> 6)) * 256 + n0 + n) * 64;
            }
#pragma unroll
            for (int d4 = 0; d4 < 64; d4 += 4) {
                uint2 t;
                t.x = (sC[(hh * 64 + d4 + 0) * 129 + n] & 0xFFFFu) | (sC[(hh * 64 + d4 + 1) * 129 + n] << 16);
                t.y = (sC[(hh * 64 + d4 + 2) * 129 + n] & 0xFFFFu) | (sC[(hh * 64 + d4 + 3) * 129 + n] << 16);
                *(uint2*)&dsth[base + d4] = t;
            }
        }
    }
}

// ---------------------------------------------------------------------------
// Cross attention v3: fp16 2-term, 2 KV chunks + online softmax.
// smem 73.7KB. Q split (Qh,Ql); K,V single plane.
// ---------------------------------------------------------------------------
#define ATT_SMEM 73728

__global__ __launch_bounds__(256, 2) void attn_kernel()
{
    extern __shared__ char smx[];
    __half* Qh = (__half*)(smx);            // 128*72*2 = 18432
    __half* Ql = (__half*)(smx + 18432);
    __half* Ks = (__half*)(smx + 36864);
    __half* Vs = (__half*)(smx + 55296);
    float* Ost = (float*)smx;               // 33280, overlays Qh/Ql

    int bid = blockIdx.x;
    int qt = bid & 7, bhs = bid >> 3;
    int s = bhs >> 7, bh = bhs & 127, h = bh & 7, b = bh >> 3;

    const unsigned* qp = g_q + ((long)(s * 128 + bh) * 1024 + qt * 128) * 64;
    const __half* kp = g_k + (long)((1 - s) * 128 + bh) * 256 * 64;
    const __half* vp = g_v + (long)((1 - s) * 128 + bh) * 256 * 64;

    int tid = threadIdx.x, lane = tid & 31, w = tid >> 5;
    int r0 = w * 16;
    int krow = (lane & 7) + ((lane >> 4) << 3);

    // Q load + de-interleave (fp16 pairs)
    for (int c = tid; c < 2048; c += 256) {
        int row = c >> 4, seg = (c & 15) * 4;
        uint4 u = *(const uint4*)&qp[row * 64 + seg];
        *(uint2*)&Qh[row * 72 + seg] = make_uint2(__byte_perm(u.x, u.y, 0x5410), __byte_perm(u.z, u.w, 0x5410));
        *(uint2*)&Ql[row * 72 + seg] = make_uint2(__byte_perm(u.x, u.y, 0x7632), __byte_perm(u.z, u.w, 0x7632));
    }

    float oreg[8][4] = {};
    float mrow0 = -1e30f, mrow1 = -1e30f, sum0 = 0.f, sum1 = 0.f;

    for (int ch = 0; ch < 2; ch++) {
        if (ch) __syncthreads();

        // K,V chunk: straight copies (single plane, 128 rows x 64 halves)
        for (int c = tid; c < 1024; c += 256) {
            int row = c >> 3, sg = (c & 7) * 8;
            *(uint4*)&Ks[row * 72 + sg] = *(const uint4*)&kp[(ch * 128 + row) * 64 + sg];
            *(uint4*)&Vs[row * 72 + sg] = *(const uint4*)&vp[(ch * 128 + row) * 64 + sg];
        }
        __syncthreads();

        // ---- S chunk = (Qh+Ql) @ Kc^T  (2 terms)
        float sreg[16][4];
#pragma unroll
        for (int nt = 0; nt < 16; nt++) {
            sreg[nt][0] = 0.f; sreg[nt][1] = 0.f; sreg[nt][2] = 0.f; sreg[nt][3] = 0.f;
        }
        for (int kk = 0; kk < 4; kk++) {
            unsigned ah[4], al[4];
            int qoff = (r0 + (lane & 15)) * 72 + kk * 16 + (lane >> 4) * 8;
            LDSM_X4(ah, &Qh[qoff]);
            LDSM_X4(al, &Ql[qoff]);
            int koff = kk * 16 + ((lane >> 3) & 1) * 8;
#pragma unroll
            for (int nt4 = 0; nt4 < 4; nt4++) {
                unsigned khA[4], khB[4];
                LDSM_X4(khA, &Ks[((2 * nt4) * 16 + krow) * 72 + koff]);
                LDSM_X4(khB, &Ks[((2 * nt4 + 1) * 16 + krow) * 72 + koff]);
                float* s0 = sreg[4 * nt4 + 0];
                float* s1 = sreg[4 * nt4 + 1];
                float* s2 = sreg[4 * nt4 + 2];
                float* s3 = sreg[4 * nt4 + 3];
                MMA_F16(s0, ah, (khA + 0)); MMA_F16(s1, ah, (khA + 2));
                MMA_F16(s2, ah, (khB + 0)); MMA_F16(s3, ah, (khB + 2));
                MMA_F16(s0, al, (khA + 0)); MMA_F16(s1, al, (khA + 2));
                MMA_F16(s2, al, (khB + 0)); MMA_F16(s3, al, (khB + 2));
            }
        }

        // ---- online softmax update
        {
            float mc0 = -1e30f, mc1 = -1e30f;
#pragma unroll
            for (int nt = 0; nt < 16; nt++) {
                mc0 = fmaxf(mc0, fmaxf(sreg[nt][0], sreg[nt][1]));
                mc1 = fmaxf(mc1, fmaxf(sreg[nt][2], sreg[nt][3]));
            }
            mc0 = fmaxf(mc0, __shfl_xor_sync(0xffffffffu, mc0, 1));
            mc0 = fmaxf(mc0, __shfl_xor_sync(0xffffffffu, mc0, 2));
            mc1 = fmaxf(mc1, __shfl_xor_sync(0xffffffffu, mc1, 1));
            mc1 = fmaxf(mc1, __shfl_xor_sync(0xffffffffu, mc1, 2));
            float mn0 = fmaxf(mrow0, mc0), mn1 = fmaxf(mrow1, mc1);
            float f0 = __expf(mrow0 - mn0), f1 = __expf(mrow1 - mn1);
            mrow0 = mn0; mrow1 = mn1;

            float cs0 = 0.f, cs1 = 0.f;
#pragma unroll
            for (int nt = 0; nt < 16; nt++) {
                float e0 = __expf(sreg[nt][0] - mn0); sreg[nt][0] = e0; cs0 += e0;
                float e1 = __expf(sreg[nt][1] - mn0); sreg[nt][1] = e1; cs0 += e1;
                float e2 = __expf(sreg[nt][2] - mn1); sreg[nt][2] = e2; cs1 += e2;
                float e3 = __expf(sreg[nt][3] - mn1); sreg[nt][3] = e3; cs1 += e3;
            }
            cs0 += __shfl_xor_sync(0xffffffffu, cs0, 1);
            cs0 += __shfl_xor_sync(0xffffffffu, cs0, 2);
            cs1 += __shfl_xor_sync(0xffffffffu, cs1, 1);
            cs1 += __shfl_xor_sync(0xffffffffu, cs1, 2);
            sum0 = sum0 * f0 + cs0;
            sum1 = sum1 * f1 + cs1;
#pragma unroll
            for (int nd = 0; nd < 8; nd++) {
                oreg[nd][0] *= f0; oreg[nd][1] *= f0;
                oreg[nd][2] *= f1; oreg[nd][3] *= f1;
            }
        }

        // ---- O += (Ph+Pl) @ Vc  (2 terms)
#pragma unroll
        for (int kt = 0; kt < 8; kt++) {
            unsigned pah[4], pal[4];
            pack2h(sreg[2 * kt][0],     sreg[2 * kt][1],     pah[0], pal[0]);
            pack2h(sreg[2 * kt][2],     sreg[2 * kt][3],     pah[1], pal[1]);
            pack2h(sreg[2 * kt + 1][0], sreg[2 * kt + 1][1], pah[2], pal[2]);
            pack2h(sreg[2 * kt + 1][2], sreg[2 * kt + 1][3], pah[3], pal[3]);
            int vrow = kt * 16 + (lane & 7) + ((lane >> 3) & 1) * 8;
            int vcol = (lane >> 4) << 3;
#pragma unroll
            for (int np = 0; np < 2; np++) {
                unsigned vhA[4], vhB[4];
                LDSM_X4T(vhA, &Vs[vrow * 72 + (2 * np) * 16 + vcol]);
                LDSM_X4T(vhB, &Vs[vrow * 72 + (2 * np + 1) * 16 + vcol]);
                float* o0 = oreg[4 * np + 0];
                float* o1 = oreg[4 * np + 1];
                float* o2 = oreg[4 * np + 2];
                float* o3 = oreg[4 * np + 3];
                MMA_F16(o0, pah, (vhA + 0)); MMA_F16(o1, pah, (vhA + 2));
                MMA_F16(o2, pah, (vhB + 0)); MMA_F16(o3, pah, (vhB + 2));
                MMA_F16(o0, pal, (vhA + 0)); MMA_F16(o1, pal, (vhA + 2));
                MMA_F16(o2, pal, (vhB + 0)); MMA_F16(o3, pal, (vhB + 2));
            }
        }
    }

    // ---- normalize, stage (Ost overlays Q planes), transposed coalesced write
    float inv0 = 1.f / sum0, inv1 = 1.f / sum1;
    __syncthreads();
    int r = lane >> 2, cc = (lane & 3) * 2;
#pragma unroll
    for (int nd = 0; nd < 8; nd++) {
        Ost[(r0 + r) * 65 + nd * 8 + cc]         = oreg[nd][0] * inv0;
        Ost[(r0 + r) * 65 + nd * 8 + cc + 1]     = oreg[nd][1] * inv0;
        Ost[(r0 + r + 8) * 65 + nd * 8 + cc]     = oreg[nd][2] * inv1;
        Ost[(r0 + r + 8) * 65 + nd * 8 + cc + 1] = oreg[nd][3] * inv1;
    }
    __syncthreads();

    unsigned* op = g_o + ((long)(s * 16 + b) * 512 + h * 64) * 1024 + qt * 128;
    int plane = lane * 4;
    for (int dd = w; dd < 64; dd += 8) {
        uint4 t;
        t.x = pack_pair(Ost[(plane + 0) * 65 + dd]);
        t.y = pack_pair(Ost[(plane + 1) * 65 + dd]);
        t.z = pack_pair(Ost[(plane + 2) * 65 + dd]);
        t.w = pack_pair(Ost[(plane + 3) * 65 + dd]);
        *(uint4*)&op[(long)dd * 1024 + plane] = t;
    }
}

// ---------------------------------------------------------------------------
// Orchestration.
// ---------------------------------------------------------------------------
extern "C" void kernel_launch(void* const* d_in, const int* in_sizes, int n_in,
                              void* d_out, int out_size)
{
    (void)in_sizes; (void)n_in; (void)out_size;
    #define F(i) ((const float*)d_in[i])

    cudaFuncSetAttribute(mma_gemm, cudaFuncAttributeMaxDynamicSharedMemorySize, GEMM_SMEM);
    cudaFuncSetAttribute(attn_kernel, cudaFuncAttributeMaxDynamicSharedMemorySize, ATT_SMEM);

    split_all_kernel<<<4096, 256>>>(F(7), F(19), F(13), F(25), F(26), F(28));

    int tot1 = 16 * 256 * 1024;
    int tot2 = 16 * 256 * 256;
    dwconv2_kernel<<<dim3((tot1 + 255) / 256, 2), 256>>>(
        F(0), F(1), F(2), F(3), F(4), F(5), F(6),
        F(14), F(15), F(16), F(17), F(18), 0, 1, 32);
    dwconv2_kernel<<<dim3((tot2 + 255) / 256, 2), 256>>>(
        F(0), F(1), F(8), F(9), F(10), F(11), F(12),
        F(20), F(21), F(22), F(23), F(24), 1, 2, 16);

    // q projection  [512,1024]
    mma_gemm<<<dim3(1024 / BN, 512 / BM, 32), 256, GEMM_SMEM>>>(512, 1024, 256, 0, nullptr, nullptr, nullptr);
    // kv projection [1024,256]
    mma_gemm<<<dim3(256 / BN, 1024 / BM, 32), 256, GEMM_SMEM>>>(1024, 256, 256, 1, nullptr, nullptr, nullptr);

    // attention (fp16 2-term)
    attn_kernel<<<2048, 256, ATT_SMEM>>>();

    // out projection [256,1024]
    mma_gemm<<<dim3(1024 / BN, 256 / BM, 32), 256, GEMM_SMEM>>>(256, 1024, 512, 2, (float*)d_out, F(27), F(29));

    #undef F
}

// round 15
// speedup vs baseline: 1.6108x; 1.1633x over previous
#include <cuda_runtime.h>
#include <cuda_bf16.h>
#include <cuda_fp16.h>
#include <stdint.h>
#include <math.h>

// ---------------------------------------------------------------------------
// ConvCrossAttention. R15: fp16 2-term everywhere.
// Weights: fp16 hi/lo split. Activations: single fp16. 2 MMAs per tile-term.
// Attention: Q,P split fp16; K,V single fp16 (as R14).
// ---------------------------------------------------------------------------

__device__ __half   g_yq [2*16*256*1024];  // dwconv q path  [z][c][p] fp16
__device__ __half   g_ykv[2*16*256*256];   // dwconv kv path
__device__ unsigned g_q  [2*16*8*1024*64]; // fp16 pairs (hi|lo<<16), scale folded
__device__ __half   g_k  [2*16*8*256*64];  // single fp16
__device__ __half   g_v  [2*16*8*256*64];
__device__ __half   g_o  [2*16*512*1024];  // attn out fp16 [z][c][p]
__device__ __half g_wq_hi [2*512*256],  g_wq_lo [2*512*256];
__device__ __half g_wkv_hi[2*1024*256], g_wkv_lo[2*1024*256];
__device__ __half g_wo_hi [2*256*512],  g_wo_lo [2*256*512];

__device__ __forceinline__ unsigned pack_pair_h(float v)   // fp16 pair
{
    __half2 p;
    p.x = __float2half(v);
    p.y = __float2half(v - __half2float(p.x));
    return *(unsigned*)&p;
}

__device__ __forceinline__ void pack2h(float a, float b, unsigned& hi, unsigned& lo)
{
    __half2 h = __floats2half2_rn(a, b);
    __half2 l = __floats2half2_rn(a - __half2float(h.x), b - __half2float(h.y));
    hi = *(unsigned*)&h;
    lo = *(unsigned*)&l;
}

// ---------------------------------------------------------------------------
__global__ void split_all_kernel(const float* __restrict__ wq0, const float* __restrict__ wq1,
                                 const float* __restrict__ wkv0, const float* __restrict__ wkv1,
                                 const float* __restrict__ wo0, const float* __restrict__ wo1)
{
    int i = blockIdx.x * blockDim.x + threadIdx.x;
    const float* src;
    __half *hi, *lo;
    int dst;
    float scale = 1.0f;
    if (i < 262144) {
        src = (i >= 131072) ? wq1 + (i - 131072) : wq0 + i;
        hi = g_wq_hi; lo = g_wq_lo; dst = i; scale = 0.125f;
    } else if (i < 786432) {
        int j = i - 262144;
        src = (j >= 262144) ? wkv1 + (j - 262144) : wkv0 + j;
        hi = g_wkv_hi; lo = g_wkv_lo; dst = j;
    } else {
        int j = i - 786432;
        src = (j >= 131072) ? wo1 + (j - 131072) : wo0 + j;
        hi = g_wo_hi; lo = g_wo_lo; dst = j;
    }
    float v = *src * scale;
    __half h = __float2half(v);
    hi[dst] = h;
    lo[dst] = __float2half(v - __half2float(h));
}

// ---------------------------------------------------------------------------
__global__ void dwconv2_kernel(const float* __restrict__ x0, const float* __restrict__ x1,
                               const float* __restrict__ dw0, const float* __restrict__ g0,
                               const float* __restrict__ b0, const float* __restrict__ rm0,
                               const float* __restrict__ rv0,
                               const float* __restrict__ dw1, const float* __restrict__ g1,
                               const float* __restrict__ b1, const float* __restrict__ rm1,
                               const float* __restrict__ rv1,
                               int dst_kv, int stride, int OH)
{
    int idx = blockIdx.x * blockDim.x + threadIdx.x;
    int total = 16 * 256 * OH * OH;
    if (idx >= total) return;
    int sp = blockIdx.y;
    const float* x  = sp ? x1 : x0;
    const float* dw = sp ? dw1 : dw0;
    const float* gam = sp ? g1 : g0;
    const float* bet = sp ? b1 : b0;
    const float* rm = sp ? rm1 : rm0;
    const float* rv = sp ? rv1 : rv0;

    int ox = idx % OH; int t = idx / OH;
    int oy = t % OH;   t /= OH;
    int c = t & 255;   int b = t >> 8;

    const float* xp = x + ((b << 8) | c) * 1024;
    const float* w  = dw + c * 9;
    int iy0 = oy * stride - 1, ix0 = ox * stride - 1;
    float acc = 0.f;
#pragma unroll
    for (int ky = 0; ky < 3; ky++) {
        int iy = iy0 + ky;
        if ((unsigned)iy < 32u) {
#pragma unroll
            for (int kx = 0; kx < 3; kx++) {
                int ix = ix0 + kx;
                if ((unsigned)ix < 32u) acc += xp[iy * 32 + ix] * w[ky * 3 + kx];
            }
        }
    }
    float inv = gam[c] * rsqrtf(rv[c] + 1e-5f);
    float r = acc * inv + (bet[c] - rm[c] * inv);
    __half* y = dst_kv ? g_ykv : g_yq;
    y[sp * total + idx] = __float2half(r);
}

// ---------------------------------------------------------------------------
// MMA primitives
// ---------------------------------------------------------------------------
#define MMA_F16(d, a, b) asm volatile( \
    "mma.sync.aligned.m16n8k16.row.col.f32.f16.f16.f32 " \
    "{%0,%1,%2,%3}, {%4,%5,%6,%7}, {%8,%9}, {%0,%1,%2,%3};" \
    : "+f"(d[0]), "+f"(d[1]), "+f"(d[2]), "+f"(d[3]) \
    : "r"(a[0]), "r"(a[1]), "r"(a[2]), "r"(a[3]), "r"(b[0]), "r"(b[1]))

#define LDSM_X4(R, p) { unsigned _ad = (unsigned)__cvta_generic_to_shared(p); \
    asm volatile("ldmatrix.sync.aligned.m8n8.x4.shared.b16 {%0,%1,%2,%3}, [%4];" \
        : "=r"(R[0]), "=r"(R[1]), "=r"(R[2]), "=r"(R[3]) : "r"(_ad)); }

#define LDSM_X4T(R, p) { unsigned _ad = (unsigned)__cvta_generic_to_shared(p); \
    asm volatile("ldmatrix.sync.aligned.m8n8.x4.trans.shared.b16 {%0,%1,%2,%3}, [%4];" \
        : "=r"(R[0]), "=r"(R[1]), "=r"(R[2]), "=r"(R[3]) : "r"(_ad)); }

#define CP_ASYNC16(smem_u32, gptr) \
    asm volatile("cp.async.cg.shared.global [%0], [%1], 16;" :: "r"(smem_u32), "l"(gptr))
#define CP_COMMIT() asm volatile("cp.async.commit_group;")
#define CP_WAIT0()  asm volatile("cp.async.wait_group 0;")

// ---------------------------------------------------------------------------
// Pipelined fp16 2-term GEMM: C[z] = (Wh+Wl) [M,K] @ B[z] [K,N], B single fp16.
// 128x128 tile, BK=32, 256 threads (8 warps 2x4). All loads via cp.async.
// mode 0 -> g_q (fp16 pairs), mode 1 -> g_k/g_v (fp16), mode 2 -> fp32+bias.
// ---------------------------------------------------------------------------
#define BM 128
#define BN 128
#define BK 32
#define SA_STR 40
#define SB_STR 136
#define A_PLANE 10240
#define B_PLANE 8704
#define BUF_BYTES 29184
#define GEMM_SMEM 66048   // 2 buffers (58368); sC epilogue 128*129*4 overlays

__global__ __launch_bounds__(256) void mma_gemm(int M, int N, int K, int mode,
                                                float* __restrict__ Ob,
                                                const float* __restrict__ bias0,
                                                const float* __restrict__ bias1)
{
    extern __shared__ char gsm[];
    unsigned* sC = (unsigned*)gsm;

    int z = blockIdx.z, s = z >> 4;
    const __half *Ahp, *Alp, *Bp;
    if (mode == 0) {
        Ahp = g_wq_hi  + s * 512 * 256;  Alp = g_wq_lo  + s * 512 * 256;
        Bp = g_yq  + (long)z * 256 * 1024;
    } else if (mode == 1) {
        Ahp = g_wkv_hi + s * 1024 * 256; Alp = g_wkv_lo + s * 1024 * 256;
        Bp = g_ykv + (long)z * 256 * 256;
    } else {
        Ahp = g_wo_hi  + s * 256 * 512;  Alp = g_wo_lo  + s * 256 * 512;
        Bp = g_o   + (long)z * 512 * 1024;
    }

    int m0 = blockIdx.y * BM, n0 = blockIdx.x * BN;
    int tid = threadIdx.x, lane = tid & 31, wid = tid >> 5;
    int wm = wid >> 2, wn = wid & 3;

    float acc[4][4][4] = {};

    int arow = tid >> 2, acol = (tid & 3) * 8;
    int lr = lane & 15, lc = (lane >> 4) * 8;
    int brow2 = (lane & 7) + ((lane >> 3) & 1) * 8;
    int bcol2 = (lane >> 4) * 8;

    __half* pAh[2] = {(__half*)gsm, (__half*)(gsm + BUF_BYTES)};
    __half* pAl[2] = {(__half*)(gsm + A_PLANE), (__half*)(gsm + BUF_BYTES + A_PLANE)};
    __half* pB [2] = {(__half*)(gsm + 2*A_PLANE), (__half*)(gsm + BUF_BYTES + 2*A_PLANE)};

    int nk = K / BK;
    int bR[2], bC[2];
#pragma unroll
    for (int j = 0; j < 2; j++) { int sj = tid + 256 * j; bR[j] = sj >> 4; bC[j] = (sj & 15) * 8; }

    // prologue: buffer 0
    {
#pragma unroll
        for (int r = 0; r < 2; r++) {
            unsigned d0 = (unsigned)__cvta_generic_to_shared(&pAh[0][(arow + 64 * r) * SA_STR + acol]);
            unsigned d1 = (unsigned)__cvta_generic_to_shared(&pAl[0][(arow + 64 * r) * SA_STR + acol]);
            CP_ASYNC16(d0, &Ahp[(long)(m0 + arow + 64 * r) * K + acol]);
            CP_ASYNC16(d1, &Alp[(long)(m0 + arow + 64 * r) * K + acol]);
        }
#pragma unroll
        for (int j = 0; j < 2; j++) {
            unsigned d = (unsigned)__cvta_generic_to_shared(&pB[0][bR[j] * SB_STR + bC[j]]);
            CP_ASYNC16(d, &Bp[(long)bR[j] * N + n0 + bC[j]]);
        }
        CP_COMMIT();
        CP_WAIT0();
        __syncthreads();
    }

    for (int i = 0; i < nk; i++) {
        int cur = i & 1, nxt = cur ^ 1;
        bool has_next = (i + 1 < nk);
        if (has_next) {
            int k0 = (i + 1) * BK;
#pragma unroll
            for (int r = 0; r < 2; r++) {
                unsigned d0 = (unsigned)__cvta_generic_to_shared(&pAh[nxt][(arow + 64 * r) * SA_STR + acol]);
                unsigned d1 = (unsigned)__cvta_generic_to_shared(&pAl[nxt][(arow + 64 * r) * SA_STR + acol]);
                CP_ASYNC16(d0, &Ahp[(long)(m0 + arow + 64 * r) * K + k0 + acol]);
                CP_ASYNC16(d1, &Alp[(long)(m0 + arow + 64 * r) * K + k0 + acol]);
            }
#pragma unroll
            for (int j = 0; j < 2; j++) {
                unsigned d = (unsigned)__cvta_generic_to_shared(&pB[nxt][bR[j] * SB_STR + bC[j]]);
                CP_ASYNC16(d, &Bp[(long)(k0 + bR[j]) * N + n0 + bC[j]]);
            }
            CP_COMMIT();
        }

        // compute buffer cur — 2 terms, term-major
#pragma unroll
        for (int kk = 0; kk < BK; kk += 16) {
            unsigned ah[4][4], al[4][4], b4[2][4];
#pragma unroll
            for (int mi = 0; mi < 4; mi++) {
                LDSM_X4(ah[mi], &pAh[cur][(wm * 64 + mi * 16 + lr) * SA_STR + kk + lc]);
                LDSM_X4(al[mi], &pAl[cur][(wm * 64 + mi * 16 + lr) * SA_STR + kk + lc]);
            }
#pragma unroll
            for (int ni2 = 0; ni2 < 2; ni2++)
                LDSM_X4T(b4[ni2], &pB[cur][(kk + brow2) * SB_STR + wn * 32 + ni2 * 16 + bcol2]);
#pragma unroll
            for (int mi = 0; mi < 4; mi++)
#pragma unroll
                for (int ni = 0; ni < 4; ni++) {
                    unsigned* bb = b4[ni >> 1] + (ni & 1) * 2;
                    MMA_F16(acc[mi][ni], ah[mi], bb);
                }
#pragma unroll
            for (int mi = 0; mi < 4; mi++)
#pragma unroll
                for (int ni = 0; ni < 4; ni++) {
                    unsigned* bb = b4[ni >> 1] + (ni & 1) * 2;
                    MMA_F16(acc[mi][ni], al[mi], bb);
                }
        }

        if (has_next) CP_WAIT0();
        __syncthreads();
    }

    int r = lane >> 2, cc = (lane & 3) * 2;
    if (mode == 2) {
        const float* bias = s ? bias1 : bias0;
#pragma unroll
        for (int mi = 0; mi < 4; mi++)
#pragma unroll
            for (int ni = 0; ni < 4; ni++)
#pragma unroll
                for (int half = 0; half < 2; half++) {
                    int m = m0 + wm * 64 + mi * 16 + r + half * 8;
                    int n = n0 + wn * 32 + ni * 8 + cc;
                    float bv = bias[m];
                    float2 v = make_float2(acc[mi][ni][half * 2] + bv,
                                           acc[mi][ni][half * 2 + 1] + bv);
                    *(float2*)&Ob[((long)z * M + m) * N + n] = v;
                }
    } else {
#pragma unroll
        for (int mi = 0; mi < 4; mi++)
#pragma unroll
            for (int ni = 0; ni < 4; ni++)
#pragma unroll
                for (int half = 0; half < 2; half++) {
                    int ml = wm * 64 + mi * 16 + r + half * 8;
                    int nl = wn * 32 + ni * 8 + cc;
                    if (mode == 0) {
                        sC[ml * 129 + nl]     = pack_pair_h(acc[mi][ni][half * 2]);
                        sC[ml * 129 + nl + 1] = pack_pair_h(acc[mi][ni][half * 2 + 1]);
                    } else {
                        sC[ml * 129 + nl]     = (unsigned)__half_as_ushort(__float2half(acc[mi][ni][half * 2]));
                        sC[ml * 129 + nl + 1] = (unsigned)__half_as_ushort(__float2half(acc[mi][ni][half * 2 + 1]));
                    }
                }
        __syncthreads();

        int n = tid & 127, hh = tid >> 7;
        int mrow = m0 + hh * 64;
        if (mode == 0) {
            long base = ((long)(z * 8 + (mrow >> 6)) * 1024 + n0 + n) * 64;
#pragma unroll
            for (int d4 = 0; d4 < 64; d4 += 4) {
                uint4 t;
                t.x = sC[(hh * 64 + d4 + 0) * 129 + n];
                t.y = sC[(hh * 64 + d4 + 1) * 129 + n];
                t.z = sC[(hh * 64 + d4 + 2) * 129 + n];
                t.w = sC[(hh * 64 + d4 + 3) * 129 + n];
                *(uint4*)&g_q[base + d4] = t;
            }
        } else {
            __half* dsth;
            long base;
            if (mrow < 512) {
                dsth = g_k;
                base = ((long)(z * 8 + (mrow >> 6)) * 256 + n0 + n) * 64;
            } else {
                dsth = g_v;
                base = ((long)(z * 8 + ((mrow - 512) >> 6)) * 256 + n0 + n) * 64;
            }
#pragma unroll
            for (int d4 = 0; d4 < 64; d4 += 4) {
                uint2 t;
                t.x = (sC[(hh * 64 + d4 + 0) * 129 + n] & 0xFFFFu) | (sC[(hh * 64 + d4 + 1) * 129 + n] << 16);
                t.y = (sC[(hh * 64 + d4 + 2) * 129 + n] & 0xFFFFu) | (sC[(hh * 64 + d4 + 3) * 129 + n] << 16);
                *(uint2*)&dsth[base + d4] = t;
            }
        }
    }
}

// ---------------------------------------------------------------------------
// Cross attention: fp16 2-term, 2 KV chunks + online softmax (as R14).
// O written as single fp16 to g_o.
// ---------------------------------------------------------------------------
#define ATT_SMEM 73728

__global__ __launch_bounds__(256, 2) void attn_kernel()
{
    extern __shared__ char smx[];
    __half* Qh = (__half*)(smx);            // 128*72*2 = 18432
    __half* Ql = (__half*)(smx + 18432);
    __half* Ks = (__half*)(smx + 36864);
    __half* Vs = (__half*)(smx + 55296);
    float* Ost = (float*)smx;               // 33280, overlays Qh/Ql

    int bid = blockIdx.x;
    int qt = bid & 7, bhs = bid >> 3;
    int s = bhs >> 7, bh = bhs & 127, h = bh & 7, b = bh >> 3;

    const unsigned* qp = g_q + ((long)(s * 128 + bh) * 1024 + qt * 128) * 64;
    const __half* kp = g_k + (long)((1 - s) * 128 + bh) * 256 * 64;
    const __half* vp = g_v + (long)((1 - s) * 128 + bh) * 256 * 64;

    int tid = threadIdx.x, lane = tid & 31, w = tid >> 5;
    int r0 = w * 16;
    int krow = (lane & 7) + ((lane >> 4) << 3);

    for (int c = tid; c < 2048; c += 256) {
        int row = c >> 4, seg = (c & 15) * 4;
        uint4 u = *(const uint4*)&qp[row * 64 + seg];
        *(uint2*)&Qh[row * 72 + seg] = make_uint2(__byte_perm(u.x, u.y, 0x5410), __byte_perm(u.z, u.w, 0x5410));
        *(uint2*)&Ql[row * 72 + seg] = make_uint2(__byte_perm(u.x, u.y, 0x7632), __byte_perm(u.z, u.w, 0x7632));
    }

    float oreg[8][4] = {};
    float mrow0 = -1e30f, mrow1 = -1e30f, sum0 = 0.f, sum1 = 0.f;

    for (int ch = 0; ch < 2; ch++) {
        if (ch) __syncthreads();

        for (int c = tid; c < 1024; c += 256) {
            int row = c >> 3, sg = (c & 7) * 8;
            *(uint4*)&Ks[row * 72 + sg] = *(const uint4*)&kp[(ch * 128 + row) * 64 + sg];
            *(uint4*)&Vs[row * 72 + sg] = *(const uint4*)&vp[(ch * 128 + row) * 64 + sg];
        }
        __syncthreads();

        float sreg[16][4];
#pragma unroll
        for (int nt = 0; nt < 16; nt++) {
            sreg[nt][0] = 0.f; sreg[nt][1] = 0.f; sreg[nt][2] = 0.f; sreg[nt][3] = 0.f;
        }
        for (int kk = 0; kk < 4; kk++) {
            unsigned ah[4], al[4];
            int qoff = (r0 + (lane & 15)) * 72 + kk * 16 + (lane >> 4) * 8;
            LDSM_X4(ah, &Qh[qoff]);
            LDSM_X4(al, &Ql[qoff]);
            int koff = kk * 16 + ((lane >> 3) & 1) * 8;
#pragma unroll
            for (int nt4 = 0; nt4 < 4; nt4++) {
                unsigned khA[4], khB[4];
                LDSM_X4(khA, &Ks[((2 * nt4) * 16 + krow) * 72 + koff]);
                LDSM_X4(khB, &Ks[((2 * nt4 + 1) * 16 + krow) * 72 + koff]);
                float* s0 = sreg[4 * nt4 + 0];
                float* s1 = sreg[4 * nt4 + 1];
                float* s2 = sreg[4 * nt4 + 2];
                float* s3 = sreg[4 * nt4 + 3];
                MMA_F16(s0, ah, (khA + 0)); MMA_F16(s1, ah, (khA + 2));
                MMA_F16(s2, ah, (khB + 0)); MMA_F16(s3, ah, (khB + 2));
                MMA_F16(s0, al, (khA + 0)); MMA_F16(s1, al, (khA + 2));
                MMA_F16(s2, al, (khB + 0)); MMA_F16(s3, al, (khB + 2));
            }
        }

        {
            float mc0 = -1e30f, mc1 = -1e30f;
#pragma unroll
            for (int nt = 0; nt < 16; nt++) {
                mc0 = fmaxf(mc0, fmaxf(sreg[nt][0], sreg[nt][1]));
                mc1 = fmaxf(mc1, fmaxf(sreg[nt][2], sreg[nt][3]));
            }
            mc0 = fmaxf(mc0, __shfl_xor_sync(0xffffffffu, mc0, 1));
            mc0 = fmaxf(mc0, __shfl_xor_sync(0xffffffffu, mc0, 2));
            mc1 = fmaxf(mc1, __shfl_xor_sync(0xffffffffu, mc1, 1));
            mc1 = fmaxf(mc1, __shfl_xor_sync(0xffffffffu, mc1, 2));
            float mn0 = fmaxf(mrow0, mc0), mn1 = fmaxf(mrow1, mc1);
            float f0 = __expf(mrow0 - mn0), f1 = __expf(mrow1 - mn1);
            mrow0 = mn0; mrow1 = mn1;

            float cs0 = 0.f, cs1 = 0.f;
#pragma unroll
            for (int nt = 0; nt < 16; nt++) {
                float e0 = __expf(sreg[nt][0] - mn0); sreg[nt][0] = e0; cs0 += e0;
                float e1 = __expf(sreg[nt][1] - mn0); sreg[nt][1] = e1; cs0 += e1;
                float e2 = __expf(sreg[nt][2] - mn1); sreg[nt][2] = e2; cs1 += e2;
                float e3 = __expf(sreg[nt][3] - mn1); sreg[nt][3] = e3; cs1 += e3;
            }
            cs0 += __shfl_xor_sync(0xffffffffu, cs0, 1);
            cs0 += __shfl_xor_sync(0xffffffffu, cs0, 2);
            cs1 += __shfl_xor_sync(0xffffffffu, cs1, 1);
            cs1 += __shfl_xor_sync(0xffffffffu, cs1, 2);
            sum0 = sum0 * f0 + cs0;
            sum1 = sum1 * f1 + cs1;
#pragma unroll
            for (int nd = 0; nd < 8; nd++) {
                oreg[nd][0] *= f0; oreg[nd][1] *= f0;
                oreg[nd][2] *= f1; oreg[nd][3] *= f1;
            }
        }

#pragma unroll
        for (int kt = 0; kt < 8; kt++) {
            unsigned pah[4], pal[4];
            pack2h(sreg[2 * kt][0],     sreg[2 * kt][1],     pah[0], pal[0]);
            pack2h(sreg[2 * kt][2],     sreg[2 * kt][3],     pah[1], pal[1]);
            pack2h(sreg[2 * kt + 1][0], sreg[2 * kt + 1][1], pah[2], pal[2]);
            pack2h(sreg[2 * kt + 1][2], sreg[2 * kt + 1][3], pah[3], pal[3]);
            int vrow = kt * 16 + (lane & 7) + ((lane >> 3) & 1) * 8;
            int vcol = (lane >> 4) << 3;
#pragma unroll
            for (int np = 0; np < 2; np++) {
                unsigned vhA[4], vhB[4];
                LDSM_X4T(vhA, &Vs[vrow * 72 + (2 * np) * 16 + vcol]);
                LDSM_X4T(vhB, &Vs[vrow * 72 + (2 * np + 1) * 16 + vcol]);
                float* o0 = oreg[4 * np + 0];
                float* o1 = oreg[4 * np + 1];
                float* o2 = oreg[4 * np + 2];
                float* o3 = oreg[4 * np + 3];
                MMA_F16(o0, pah, (vhA + 0)); MMA_F16(o1, pah, (vhA + 2));
                MMA_F16(o2, pah, (vhB + 0)); MMA_F16(o3, pah, (vhB + 2));
                MMA_F16(o0, pal, (vhA + 0)); MMA_F16(o1, pal, (vhA + 2));
                MMA_F16(o2, pal, (vhB + 0)); MMA_F16(o3, pal, (vhB + 2));
            }
        }
    }

    float inv0 = 1.f / sum0, inv1 = 1.f / sum1;
    __syncthreads();
    int r = lane >> 2, cc = (lane & 3) * 2;
#pragma unroll
    for (int nd = 0; nd < 8; nd++) {
        Ost[(r0 + r) * 65 + nd * 8 + cc]         = oreg[nd][0] * inv0;
        Ost[(r0 + r) * 65 + nd * 8 + cc + 1]     = oreg[nd][1] * inv0;
        Ost[(r0 + r + 8) * 65 + nd * 8 + cc]     = oreg[nd][2] * inv1;
        Ost[(r0 + r + 8) * 65 + nd * 8 + cc + 1] = oreg[nd][3] * inv1;
    }
    __syncthreads();

    __half* op = g_o + ((long)(s * 16 + b) * 512 + h * 64) * 1024 + qt * 128;
    int plane = lane * 4;
    for (int dd = w; dd < 64; dd += 8) {
        __half2 v0 = __floats2half2_rn(Ost[(plane + 0) * 65 + dd], Ost[(plane + 1) * 65 + dd]);
        __half2 v1 = __floats2half2_rn(Ost[(plane + 2) * 65 + dd], Ost[(plane + 3) * 65 + dd]);
        uint2 t = make_uint2(*(unsigned*)&v0, *(unsigned*)&v1);
        *(uint2*)&op[(long)dd * 1024 + plane] = t;
    }
}

// ---------------------------------------------------------------------------
// Orchestration.
// ---------------------------------------------------------------------------
extern "C" void kernel_launch(void* const* d_in, const int* in_sizes, int n_in,
                              void* d_out, int out_size)
{
    (void)in_sizes; (void)n_in; (void)out_size;
    #define F(i) ((const float*)d_in[i])

    cudaFuncSetAttribute(mma_gemm, cudaFuncAttributeMaxDynamicSharedMemorySize, GEMM_SMEM);
    cudaFuncSetAttribute(attn_kernel, cudaFuncAttributeMaxDynamicSharedMemorySize, ATT_SMEM);

    split_all_kernel<<<4096, 256>>>(F(7), F(19), F(13), F(25), F(26), F(28));

    int tot1 = 16 * 256 * 1024;
    int tot2 = 16 * 256 * 256;
    dwconv2_kernel<<<dim3((tot1 + 255) / 256, 2), 256>>>(
        F(0), F(1), F(2), F(3), F(4), F(5), F(6),
        F(14), F(15), F(16), F(17), F(18), 0, 1, 32);
    dwconv2_kernel<<<dim3((tot2 + 255) / 256, 2), 256>>>(
        F(0), F(1), F(8), F(9), F(10), F(11), F(12),
        F(20), F(21), F(22), F(23), F(24), 1, 2, 16);

    // q projection  [512,1024]
    mma_gemm<<<dim3(1024 / BN, 512 / BM, 32), 256, GEMM_SMEM>>>(512, 1024, 256, 0, nullptr, nullptr, nullptr);
    // kv projection [1024,256]
    mma_gemm<<<dim3(256 / BN, 1024 / BM, 32), 256, GEMM_SMEM>>>(1024, 256, 256, 1, nullptr, nullptr, nullptr);

    // attention (fp16 2-term)
    attn_kernel<<<2048, 256, ATT_SMEM>>>();

    // out projection [256,1024]
    mma_gemm<<<dim3(1024 / BN, 256 / BM, 32), 256, GEMM_SMEM>>>(256, 1024, 512, 2, (float*)d_out, F(27), F(29));

    #undef F
}

// round 16
// speedup vs baseline: 1.7803x; 1.1052x over previous
#include <cuda_runtime.h>
#include <cuda_bf16.h>
#include <cuda_fp16.h>
#include <stdint.h>
#include <math.h>

// ---------------------------------------------------------------------------
// ConvCrossAttention. R16: fp16 2-term GEMMs (W split, activations single);
// attention all single-fp16 operands (Q,K,V,P) with fp32 accumulate.
// ---------------------------------------------------------------------------

__device__ __half   g_yq [2*16*256*1024];  // dwconv q path  [z][c][p] fp16
__device__ __half   g_ykv[2*16*256*256];   // dwconv kv path
__device__ __half   g_q  [2*16*8*1024*64]; // single fp16 (scale folded)
__device__ __half   g_k  [2*16*8*256*64];
__device__ __half   g_v  [2*16*8*256*64];
__device__ __half   g_o  [2*16*512*1024];  // attn out fp16 [z][c][p]
__device__ __half g_wq_hi [2*512*256],  g_wq_lo [2*512*256];
__device__ __half g_wkv_hi[2*1024*256], g_wkv_lo[2*1024*256];
__device__ __half g_wo_hi [2*256*512],  g_wo_lo [2*256*512];

// ---------------------------------------------------------------------------
__global__ void split_all_kernel(const float* __restrict__ wq0, const float* __restrict__ wq1,
                                 const float* __restrict__ wkv0, const float* __restrict__ wkv1,
                                 const float* __restrict__ wo0, const float* __restrict__ wo1)
{
    int i = blockIdx.x * blockDim.x + threadIdx.x;
    const float* src;
    __half *hi, *lo;
    int dst;
    float scale = 1.0f;
    if (i < 262144) {
        src = (i >= 131072) ? wq1 + (i - 131072) : wq0 + i;
        hi = g_wq_hi; lo = g_wq_lo; dst = i; scale = 0.125f;
    } else if (i < 786432) {
        int j = i - 262144;
        src = (j >= 262144) ? wkv1 + (j - 262144) : wkv0 + j;
        hi = g_wkv_hi; lo = g_wkv_lo; dst = j;
    } else {
        int j = i - 786432;
        src = (j >= 131072) ? wo1 + (j - 131072) : wo0 + j;
        hi = g_wo_hi; lo = g_wo_lo; dst = j;
    }
    float v = *src * scale;
    __half h = __float2half(v);
    hi[dst] = h;
    lo[dst] = __float2half(v - __half2float(h));
}

// ---------------------------------------------------------------------------
__global__ void dwconv2_kernel(const float* __restrict__ x0, const float* __restrict__ x1,
                               const float* __restrict__ dw0, const float* __restrict__ g0,
                               const float* __restrict__ b0, const float* __restrict__ rm0,
                               const float* __restrict__ rv0,
                               const float* __restrict__ dw1, const float* __restrict__ g1,
                               const float* __restrict__ b1, const float* __restrict__ rm1,
                               const float* __restrict__ rv1,
                               int dst_kv, int stride, int OH)
{
    int idx = blockIdx.x * blockDim.x + threadIdx.x;
    int total = 16 * 256 * OH * OH;
    if (idx >= total) return;
    int sp = blockIdx.y;
    const float* x  = sp ? x1 : x0;
    const float* dw = sp ? dw1 : dw0;
    const float* gam = sp ? g1 : g0;
    const float* bet = sp ? b1 : b0;
    const float* rm = sp ? rm1 : rm0;
    const float* rv = sp ? rv1 : rv0;

    int ox = idx % OH; int t = idx / OH;
    int oy = t % OH;   t /= OH;
    int c = t & 255;   int b = t >> 8;

    const float* xp = x + ((b << 8) | c) * 1024;
    const float* w  = dw + c * 9;
    int iy0 = oy * stride - 1, ix0 = ox * stride - 1;
    float acc = 0.f;
#pragma unroll
    for (int ky = 0; ky < 3; ky++) {
        int iy = iy0 + ky;
        if ((unsigned)iy < 32u) {
#pragma unroll
            for (int kx = 0; kx < 3; kx++) {
                int ix = ix0 + kx;
                if ((unsigned)ix < 32u) acc += xp[iy * 32 + ix] * w[ky * 3 + kx];
            }
        }
    }
    float inv = gam[c] * rsqrtf(rv[c] + 1e-5f);
    float r = acc * inv + (bet[c] - rm[c] * inv);
    __half* y = dst_kv ? g_ykv : g_yq;
    y[sp * total + idx] = __float2half(r);
}

// ---------------------------------------------------------------------------
// MMA primitives
// ---------------------------------------------------------------------------
#define MMA_F16(d, a, b) asm volatile( \
    "mma.sync.aligned.m16n8k16.row.col.f32.f16.f16.f32 " \
    "{%0,%1,%2,%3}, {%4,%5,%6,%7}, {%8,%9}, {%0,%1,%2,%3};" \
    : "+f"(d[0]), "+f"(d[1]), "+f"(d[2]), "+f"(d[3]) \
    : "r"(a[0]), "r"(a[1]), "r"(a[2]), "r"(a[3]), "r"(b[0]), "r"(b[1]))

#define LDSM_X4(R, p) { unsigned _ad = (unsigned)__cvta_generic_to_shared(p); \
    asm volatile("ldmatrix.sync.aligned.m8n8.x4.shared.b16 {%0,%1,%2,%3}, [%4];" \
        : "=r"(R[0]), "=r"(R[1]), "=r"(R[2]), "=r"(R[3]) : "r"(_ad)); }

#define LDSM_X4T(R, p) { unsigned _ad = (unsigned)__cvta_generic_to_shared(p); \
    asm volatile("ldmatrix.sync.aligned.m8n8.x4.trans.shared.b16 {%0,%1,%2,%3}, [%4];" \
        : "=r"(R[0]), "=r"(R[1]), "=r"(R[2]), "=r"(R[3]) : "r"(_ad)); }

#define CP_ASYNC16(smem_u32, gptr) \
    asm volatile("cp.async.cg.shared.global [%0], [%1], 16;" :: "r"(smem_u32), "l"(gptr))
#define CP_COMMIT() asm volatile("cp.async.commit_group;")
#define CP_WAIT0()  asm volatile("cp.async.wait_group 0;")

// ---------------------------------------------------------------------------
// Pipelined fp16 2-term GEMM: C[z] = (Wh+Wl) [M,K] @ B[z] [K,N], B single fp16.
// mode 0 -> g_q (fp16), mode 1 -> g_k/g_v (fp16), mode 2 -> fp32+bias.
// ---------------------------------------------------------------------------
#define BM 128
#define BN 128
#define BK 32
#define SA_STR 40
#define SB_STR 136
#define A_PLANE 10240
#define B_PLANE 8704
#define BUF_BYTES 29184
#define GEMM_SMEM 66048

__global__ __launch_bounds__(256) void mma_gemm(int M, int N, int K, int mode,
                                                float* __restrict__ Ob,
                                                const float* __restrict__ bias0,
                                                const float* __restrict__ bias1)
{
    extern __shared__ char gsm[];
    unsigned* sC = (unsigned*)gsm;

    int z = blockIdx.z, s = z >> 4;
    const __half *Ahp, *Alp, *Bp;
    if (mode == 0) {
        Ahp = g_wq_hi  + s * 512 * 256;  Alp = g_wq_lo  + s * 512 * 256;
        Bp = g_yq  + (long)z * 256 * 1024;
    } else if (mode == 1) {
        Ahp = g_wkv_hi + s * 1024 * 256; Alp = g_wkv_lo + s * 1024 * 256;
        Bp = g_ykv + (long)z * 256 * 256;
    } else {
        Ahp = g_wo_hi  + s * 256 * 512;  Alp = g_wo_lo  + s * 256 * 512;
        Bp = g_o   + (long)z * 512 * 1024;
    }

    int m0 = blockIdx.y * BM, n0 = blockIdx.x * BN;
    int tid = threadIdx.x, lane = tid & 31, wid = tid >> 5;
    int wm = wid >> 2, wn = wid & 3;

    float acc[4][4][4] = {};

    int arow = tid >> 2, acol = (tid & 3) * 8;
    int lr = lane & 15, lc = (lane >> 4) * 8;
    int brow2 = (lane & 7) + ((lane >> 3) & 1) * 8;
    int bcol2 = (lane >> 4) * 8;

    __half* pAh[2] = {(__half*)gsm, (__half*)(gsm + BUF_BYTES)};
    __half* pAl[2] = {(__half*)(gsm + A_PLANE), (__half*)(gsm + BUF_BYTES + A_PLANE)};
    __half* pB [2] = {(__half*)(gsm + 2*A_PLANE), (__half*)(gsm + BUF_BYTES + 2*A_PLANE)};

    int nk = K / BK;
    int bR[2], bC[2];
#pragma unroll
    for (int j = 0; j < 2; j++) { int sj = tid + 256 * j; bR[j] = sj >> 4; bC[j] = (sj & 15) * 8; }

    {
#pragma unroll
        for (int r = 0; r < 2; r++) {
            unsigned d0 = (unsigned)__cvta_generic_to_shared(&pAh[0][(arow + 64 * r) * SA_STR + acol]);
            unsigned d1 = (unsigned)__cvta_generic_to_shared(&pAl[0][(arow + 64 * r) * SA_STR + acol]);
            CP_ASYNC16(d0, &Ahp[(long)(m0 + arow + 64 * r) * K + acol]);
            CP_ASYNC16(d1, &Alp[(long)(m0 + arow + 64 * r) * K + acol]);
        }
#pragma unroll
        for (int j = 0; j < 2; j++) {
            unsigned d = (unsigned)__cvta_generic_to_shared(&pB[0][bR[j] * SB_STR + bC[j]]);
            CP_ASYNC16(d, &Bp[(long)bR[j] * N + n0 + bC[j]]);
        }
        CP_COMMIT();
        CP_WAIT0();
        __syncthreads();
    }

    for (int i = 0; i < nk; i++) {
        int cur = i & 1, nxt = cur ^ 1;
        bool has_next = (i + 1 < nk);
        if (has_next) {
            int k0 = (i + 1) * BK;
#pragma unroll
            for (int r = 0; r < 2; r++) {
                unsigned d0 = (unsigned)__cvta_generic_to_shared(&pAh[nxt][(arow + 64 * r) * SA_STR + acol]);
                unsigned d1 = (unsigned)__cvta_generic_to_shared(&pAl[nxt][(arow + 64 * r) * SA_STR + acol]);
                CP_ASYNC16(d0, &Ahp[(long)(m0 + arow + 64 * r) * K + k0 + acol]);
                CP_ASYNC16(d1, &Alp[(long)(m0 + arow + 64 * r) * K + k0 + acol]);
            }
#pragma unroll
            for (int j = 0; j < 2; j++) {
                unsigned d = (unsigned)__cvta_generic_to_shared(&pB[nxt][bR[j] * SB_STR + bC[j]]);
                CP_ASYNC16(d, &Bp[(long)(k0 + bR[j]) * N + n0 + bC[j]]);
            }
            CP_COMMIT();
        }

#pragma unroll
        for (int kk = 0; kk < BK; kk += 16) {
            unsigned ah[4][4], al[4][4], b4[2][4];
#pragma unroll
            for (int mi = 0; mi < 4; mi++) {
                LDSM_X4(ah[mi], &pAh[cur][(wm * 64 + mi * 16 + lr) * SA_STR + kk + lc]);
                LDSM_X4(al[mi], &pAl[cur][(wm * 64 + mi * 16 + lr) * SA_STR + kk + lc]);
            }
#pragma unroll
            for (int ni2 = 0; ni2 < 2; ni2++)
                LDSM_X4T(b4[ni2], &pB[cur][(kk + brow2) * SB_STR + wn * 32 + ni2 * 16 + bcol2]);
#pragma unroll
            for (int mi = 0; mi < 4; mi++)
#pragma unroll
                for (int ni = 0; ni < 4; ni++) {
                    unsigned* bb = b4[ni >> 1] + (ni & 1) * 2;
                    MMA_F16(acc[mi][ni], ah[mi], bb);
                }
#pragma unroll
            for (int mi = 0; mi < 4; mi++)
#pragma unroll
                for (int ni = 0; ni < 4; ni++) {
                    unsigned* bb = b4[ni >> 1] + (ni & 1) * 2;
                    MMA_F16(acc[mi][ni], al[mi], bb);
                }
        }

        if (has_next) CP_WAIT0();
        __syncthreads();
    }

    int r = lane >> 2, cc = (lane & 3) * 2;
    if (mode == 2) {
        const float* bias = s ? bias1 : bias0;
#pragma unroll
        for (int mi = 0; mi < 4; mi++)
#pragma unroll
            for (int ni = 0; ni < 4; ni++)
#pragma unroll
                for (int half = 0; half < 2; half++) {
                    int m = m0 + wm * 64 + mi * 16 + r + half * 8;
                    int n = n0 + wn * 32 + ni * 8 + cc;
                    float bv = bias[m];
                    float2 v = make_float2(acc[mi][ni][half * 2] + bv,
                                           acc[mi][ni][half * 2 + 1] + bv);
                    *(float2*)&Ob[((long)z * M + m) * N + n] = v;
                }
    } else {
#pragma unroll
        for (int mi = 0; mi < 4; mi++)
#pragma unroll
            for (int ni = 0; ni < 4; ni++)
#pragma unroll
                for (int half = 0; half < 2; half++) {
                    int ml = wm * 64 + mi * 16 + r + half * 8;
                    int nl = wn * 32 + ni * 8 + cc;
                    sC[ml * 129 + nl]     = (unsigned)__half_as_ushort(__float2half(acc[mi][ni][half * 2]));
                    sC[ml * 129 + nl + 1] = (unsigned)__half_as_ushort(__float2half(acc[mi][ni][half * 2 + 1]));
                }
        __syncthreads();

        int n = tid & 127, hh = tid >> 7;
        int mrow = m0 + hh * 64;
        __half* dsth;
        long base;
        if (mode == 0) {
            dsth = g_q;
            base = ((long)(z * 8 + (mrow >> 6)) * 1024 + n0 + n) * 64;
        } else if (mrow < 512) {
            dsth = g_k;
            base = ((long)(z * 8 + (mrow >> 6)) * 256 + n0 + n) * 64;
        } else {
            dsth = g_v;
            base = ((long)(z * 8 + ((mrow - 512) >> 6)) * 256 + n0 + n) * 64;
        }
#pragma unroll
        for (int d4 = 0; d4 < 64; d4 += 4) {
            uint2 t;
            t.x = (sC[(hh * 64 + d4 + 0) * 129 + n] & 0xFFFFu) | (sC[(hh * 64 + d4 + 1) * 129 + n] << 16);
            t.y = (sC[(hh * 64 + d4 + 2) * 129 + n] & 0xFFFFu) | (sC[(hh * 64 + d4 + 3) * 129 + n] << 16);
            *(uint2*)&dsth[base + d4] = t;
        }
    }
}

// ---------------------------------------------------------------------------
// Cross attention v4: all single-fp16 operands, 2 KV chunks + online softmax.
// smem 54KB. One CTA per (s,b,h,qt).
// ---------------------------------------------------------------------------
#define ATT_SMEM 55296

__global__ __launch_bounds__(256, 2) void attn_kernel()
{
    extern __shared__ char smx[];
    __half* Qs = (__half*)(smx);            // 128*72*2 = 18432
    __half* Ks = (__half*)(smx + 18432);
    __half* Vs = (__half*)(smx + 36864);
    float* Ost = (float*)smx;               // 33280, overlays Qs+Ks at end

    int bid = blockIdx.x;
    int qt = bid & 7, bhs = bid >> 3;
    int s = bhs >> 7, bh = bhs & 127, h = bh & 7, b = bh >> 3;

    const __half* qp = g_q + ((long)(s * 128 + bh) * 1024 + qt * 128) * 64;
    const __half* kp = g_k + (long)((1 - s) * 128 + bh) * 256 * 64;
    const __half* vp = g_v + (long)((1 - s) * 128 + bh) * 256 * 64;

    int tid = threadIdx.x, lane = tid & 31, w = tid >> 5;
    int r0 = w * 16;
    int krow = (lane & 7) + ((lane >> 4) << 3);

    // Q load: straight copies (128 rows x 64 halves)
    for (int c = tid; c < 1024; c += 256) {
        int row = c >> 3, sg = (c & 7) * 8;
        *(uint4*)&Qs[row * 72 + sg] = *(const uint4*)&qp[row * 64 + sg];
    }

    float oreg[8][4] = {};
    float mrow0 = -1e30f, mrow1 = -1e30f, sum0 = 0.f, sum1 = 0.f;

    for (int ch = 0; ch < 2; ch++) {
        if (ch) __syncthreads();

        for (int c = tid; c < 1024; c += 256) {
            int row = c >> 3, sg = (c & 7) * 8;
            *(uint4*)&Ks[row * 72 + sg] = *(const uint4*)&kp[(ch * 128 + row) * 64 + sg];
            *(uint4*)&Vs[row * 72 + sg] = *(const uint4*)&vp[(ch * 128 + row) * 64 + sg];
        }
        __syncthreads();

        // ---- S chunk = Q @ Kc^T (single term)
        float sreg[16][4];
#pragma unroll
        for (int nt = 0; nt < 16; nt++) {
            sreg[nt][0] = 0.f; sreg[nt][1] = 0.f; sreg[nt][2] = 0.f; sreg[nt][3] = 0.f;
        }
        for (int kk = 0; kk < 4; kk++) {
            unsigned aq[4];
            int qoff = (r0 + (lane & 15)) * 72 + kk * 16 + (lane >> 4) * 8;
            LDSM_X4(aq, &Qs[qoff]);
            int koff = kk * 16 + ((lane >> 3) & 1) * 8;
#pragma unroll
            for (int nt4 = 0; nt4 < 4; nt4++) {
                unsigned khA[4], khB[4];
                LDSM_X4(khA, &Ks[((2 * nt4) * 16 + krow) * 72 + koff]);
                LDSM_X4(khB, &Ks[((2 * nt4 + 1) * 16 + krow) * 72 + koff]);
                MMA_F16(sreg[4 * nt4 + 0], aq, (khA + 0));
                MMA_F16(sreg[4 * nt4 + 1], aq, (khA + 2));
                MMA_F16(sreg[4 * nt4 + 2], aq, (khB + 0));
                MMA_F16(sreg[4 * nt4 + 3], aq, (khB + 2));
            }
        }

        // ---- online softmax update
        {
            float mc0 = -1e30f, mc1 = -1e30f;
#pragma unroll
            for (int nt = 0; nt < 16; nt++) {
                mc0 = fmaxf(mc0, fmaxf(sreg[nt][0], sreg[nt][1]));
                mc1 = fmaxf(mc1, fmaxf(sreg[nt][2], sreg[nt][3]));
            }
            mc0 = fmaxf(mc0, __shfl_xor_sync(0xffffffffu, mc0, 1));
            mc0 = fmaxf(mc0, __shfl_xor_sync(0xffffffffu, mc0, 2));
            mc1 = fmaxf(mc1, __shfl_xor_sync(0xffffffffu, mc1, 1));
            mc1 = fmaxf(mc1, __shfl_xor_sync(0xffffffffu, mc1, 2));
            float mn0 = fmaxf(mrow0, mc0), mn1 = fmaxf(mrow1, mc1);
            float f0 = __expf(mrow0 - mn0), f1 = __expf(mrow1 - mn1);
            mrow0 = mn0; mrow1 = mn1;

            float cs0 = 0.f, cs1 = 0.f;
#pragma unroll
            for (int nt = 0; nt < 16; nt++) {
                float e0 = __expf(sreg[nt][0] - mn0); sreg[nt][0] = e0; cs0 += e0;
                float e1 = __expf(sreg[nt][1] - mn0); sreg[nt][1] = e1; cs0 += e1;
                float e2 = __expf(sreg[nt][2] - mn1); sreg[nt][2] = e2; cs1 += e2;
                float e3 = __expf(sreg[nt][3] - mn1); sreg[nt][3] = e3; cs1 += e3;
            }
            cs0 += __shfl_xor_sync(0xffffffffu, cs0, 1);
            cs0 += __shfl_xor_sync(0xffffffffu, cs0, 2);
            cs1 += __shfl_xor_sync(0xffffffffu, cs1, 1);
            cs1 += __shfl_xor_sync(0xffffffffu, cs1, 2);
            sum0 = sum0 * f0 + cs0;
            sum1 = sum1 * f1 + cs1;
#pragma unroll
            for (int nd = 0; nd < 8; nd++) {
                oreg[nd][0] *= f0; oreg[nd][1] *= f0;
                oreg[nd][2] *= f1; oreg[nd][3] *= f1;
            }
        }

        // ---- O += Pc @ Vc (single term)
#pragma unroll
        for (int kt = 0; kt < 8; kt++) {
            unsigned pa[4];
            {
                __half2 h0 = __floats2half2_rn(sreg[2 * kt][0],     sreg[2 * kt][1]);
                __half2 h1 = __floats2half2_rn(sreg[2 * kt][2],     sreg[2 * kt][3]);
                __half2 h2 = __floats2half2_rn(sreg[2 * kt + 1][0], sreg[2 * kt + 1][1]);
                __half2 h3 = __floats2half2_rn(sreg[2 * kt + 1][2], sreg[2 * kt + 1][3]);
                pa[0] = *(unsigned*)&h0; pa[1] = *(unsigned*)&h1;
                pa[2] = *(unsigned*)&h2; pa[3] = *(unsigned*)&h3;
            }
            int vrow = kt * 16 + (lane & 7) + ((lane >> 3) & 1) * 8;
            int vcol = (lane >> 4) << 3;
#pragma unroll
            for (int np = 0; np < 2; np++) {
                unsigned vhA[4], vhB[4];
                LDSM_X4T(vhA, &Vs[vrow * 72 + (2 * np) * 16 + vcol]);
                LDSM_X4T(vhB, &Vs[vrow * 72 + (2 * np + 1) * 16 + vcol]);
                MMA_F16(oreg[4 * np + 0], pa, (vhA + 0));
                MMA_F16(oreg[4 * np + 1], pa, (vhA + 2));
                MMA_F16(oreg[4 * np + 2], pa, (vhB + 0));
                MMA_F16(oreg[4 * np + 3], pa, (vhB + 2));
            }
        }
    }

    // ---- normalize, stage (Ost overlays Qs/Ks), transposed coalesced write
    float inv0 = 1.f / sum0, inv1 = 1.f / sum1;
    __syncthreads();
    int r = lane >> 2, cc = (lane & 3) * 2;
#pragma unroll
    for (int nd = 0; nd < 8; nd++) {
        Ost[(r0 + r) * 65 + nd * 8 + cc]         = oreg[nd][0] * inv0;
        Ost[(r0 + r) * 65 + nd * 8 + cc + 1]     = oreg[nd][1] * inv0;
        Ost[(r0 + r + 8) * 65 + nd * 8 + cc]     = oreg[nd][2] * inv1;
        Ost[(r0 + r + 8) * 65 + nd * 8 + cc + 1] = oreg[nd][3] * inv1;
    }
    __syncthreads();

    __half* op = g_o + ((long)(s * 16 + b) * 512 + h * 64) * 1024 + qt * 128;
    int plane = lane * 4;
    for (int dd = w; dd < 64; dd += 8) {
        __half2 v0 = __floats2half2_rn(Ost[(plane + 0) * 65 + dd], Ost[(plane + 1) * 65 + dd]);
        __half2 v1 = __floats2half2_rn(Ost[(plane + 2) * 65 + dd], Ost[(plane + 3) * 65 + dd]);
        uint2 t = make_uint2(*(unsigned*)&v0, *(unsigned*)&v1);
        *(uint2*)&op[(long)dd * 1024 + plane] = t;
    }
}

// ---------------------------------------------------------------------------
// Orchestration.
// ---------------------------------------------------------------------------
extern "C" void kernel_launch(void* const* d_in, const int* in_sizes, int n_in,
                              void* d_out, int out_size)
{
    (void)in_sizes; (void)n_in; (void)out_size;
    #define F(i) ((const float*)d_in[i])

    cudaFuncSetAttribute(mma_gemm, cudaFuncAttributeMaxDynamicSharedMemorySize, GEMM_SMEM);
    cudaFuncSetAttribute(attn_kernel, cudaFuncAttributeMaxDynamicSharedMemorySize, ATT_SMEM);

    split_all_kernel<<<4096, 256>>>(F(7), F(19), F(13), F(25), F(26), F(28));

    int tot1 = 16 * 256 * 1024;
    int tot2 = 16 * 256 * 256;
    dwconv2_kernel<<<dim3((tot1 + 255) / 256, 2), 256>>>(
        F(0), F(1), F(2), F(3), F(4), F(5), F(6),
        F(14), F(15), F(16), F(17), F(18), 0, 1, 32);
    dwconv2_kernel<<<dim3((tot2 + 255) / 256, 2), 256>>>(
        F(0), F(1), F(8), F(9), F(10), F(11), F(12),
        F(20), F(21), F(22), F(23), F(24), 1, 2, 16);

    // q projection  [512,1024]
    mma_gemm<<<dim3(1024 / BN, 512 / BM, 32), 256, GEMM_SMEM>>>(512, 1024, 256, 0, nullptr, nullptr, nullptr);
    // kv projection [1024,256]
    mma_gemm<<<dim3(256 / BN, 1024 / BM, 32), 256, GEMM_SMEM>>>(1024, 256, 256, 1, nullptr, nullptr, nullptr);

    // attention (single fp16 operands)
    attn_kernel<<<2048, 256, ATT_SMEM>>>();

    // out projection [256,1024]
    mma_gemm<<<dim3(1024 / BN, 256 / BM, 32), 256, GEMM_SMEM>>>(256, 1024, 512, 2, (float*)d_out, F(27), F(29));

    #undef F
}

// round 17
// speedup vs baseline: 2.1201x; 1.1908x over previous
#include <cuda_runtime.h>
#include <cuda_bf16.h>
#include <cuda_fp16.h>
#include <stdint.h>
#include <math.h>

// ---------------------------------------------------------------------------
// ConvCrossAttention. R17: pure single-fp16 tensor math everywhere
// (weights, activations, attention operands), fp32 accumulate.
// ---------------------------------------------------------------------------

__device__ __half g_yq [2*16*256*1024];  // dwconv q path  [z][c][p] fp16
__device__ __half g_ykv[2*16*256*256];   // dwconv kv path
__device__ __half g_q  [2*16*8*1024*64]; // fp16 (softmax scale folded)
__device__ __half g_k  [2*16*8*256*64];
__device__ __half g_v  [2*16*8*256*64];
__device__ __half g_o  [2*16*512*1024];  // attn out fp16 [z][c][p]
__device__ __half g_wq [2*512*256];
__device__ __half g_wkv[2*1024*256];
__device__ __half g_wo [2*256*512];

// ---------------------------------------------------------------------------
__global__ void split_all_kernel(const float* __restrict__ wq0, const float* __restrict__ wq1,
                                 const float* __restrict__ wkv0, const float* __restrict__ wkv1,
                                 const float* __restrict__ wo0, const float* __restrict__ wo1)
{
    int i = blockIdx.x * blockDim.x + threadIdx.x;
    const float* src;
    __half* dstp;
    int dst;
    float scale = 1.0f;
    if (i < 262144) {
        src = (i >= 131072) ? wq1 + (i - 131072) : wq0 + i;
        dstp = g_wq; dst = i; scale = 0.125f;
    } else if (i < 786432) {
        int j = i - 262144;
        src = (j >= 262144) ? wkv1 + (j - 262144) : wkv0 + j;
        dstp = g_wkv; dst = j;
    } else {
        int j = i - 786432;
        src = (j >= 131072) ? wo1 + (j - 131072) : wo0 + j;
        dstp = g_wo; dst = j;
    }
    dstp[dst] = __float2half(*src * scale);
}

// ---------------------------------------------------------------------------
__global__ void dwconv2_kernel(const float* __restrict__ x0, const float* __restrict__ x1,
                               const float* __restrict__ dw0, const float* __restrict__ g0,
                               const float* __restrict__ b0, const float* __restrict__ rm0,
                               const float* __restrict__ rv0,
                               const float* __restrict__ dw1, const float* __restrict__ g1,
                               const float* __restrict__ b1, const float* __restrict__ rm1,
                               const float* __restrict__ rv1,
                               int dst_kv, int stride, int OH)
{
    int idx = blockIdx.x * blockDim.x + threadIdx.x;
    int total = 16 * 256 * OH * OH;
    if (idx >= total) return;
    int sp = blockIdx.y;
    const float* x  = sp ? x1 : x0;
    const float* dw = sp ? dw1 : dw0;
    const float* gam = sp ? g1 : g0;
    const float* bet = sp ? b1 : b0;
    const float* rm = sp ? rm1 : rm0;
    const float* rv = sp ? rv1 : rv0;

    int ox = idx % OH; int t = idx / OH;
    int oy = t % OH;   t /= OH;
    int c = t & 255;   int b = t >> 8;

    const float* xp = x + ((b << 8) | c) * 1024;
    const float* w  = dw + c * 9;
    int iy0 = oy * stride - 1, ix0 = ox * stride - 1;
    float acc = 0.f;
#pragma unroll
    for (int ky = 0; ky < 3; ky++) {
        int iy = iy0 + ky;
        if ((unsigned)iy < 32u) {
#pragma unroll
            for (int kx = 0; kx < 3; kx++) {
                int ix = ix0 + kx;
                if ((unsigned)ix < 32u) acc += xp[iy * 32 + ix] * w[ky * 3 + kx];
            }
        }
    }
    float inv = gam[c] * rsqrtf(rv[c] + 1e-5f);
    float r = acc * inv + (bet[c] - rm[c] * inv);
    __half* y = dst_kv ? g_ykv : g_yq;
    y[sp * total + idx] = __float2half(r);
}

// ---------------------------------------------------------------------------
// MMA primitives
// ---------------------------------------------------------------------------
#define MMA_F16(d, a, b) asm volatile( \
    "mma.sync.aligned.m16n8k16.row.col.f32.f16.f16.f32 " \
    "{%0,%1,%2,%3}, {%4,%5,%6,%7}, {%8,%9}, {%0,%1,%2,%3};" \
    : "+f"(d[0]), "+f"(d[1]), "+f"(d[2]), "+f"(d[3]) \
    : "r"(a[0]), "r"(a[1]), "r"(a[2]), "r"(a[3]), "r"(b[0]), "r"(b[1]))

#define LDSM_X4(R, p) { unsigned _ad = (unsigned)__cvta_generic_to_shared(p); \
    asm volatile("ldmatrix.sync.aligned.m8n8.x4.shared.b16 {%0,%1,%2,%3}, [%4];" \
        : "=r"(R[0]), "=r"(R[1]), "=r"(R[2]), "=r"(R[3]) : "r"(_ad)); }

#define LDSM_X4T(R, p) { unsigned _ad = (unsigned)__cvta_generic_to_shared(p); \
    asm volatile("ldmatrix.sync.aligned.m8n8.x4.trans.shared.b16 {%0,%1,%2,%3}, [%4];" \
        : "=r"(R[0]), "=r"(R[1]), "=r"(R[2]), "=r"(R[3]) : "r"(_ad)); }

#define CP_ASYNC16(smem_u32, gptr) \
    asm volatile("cp.async.cg.shared.global [%0], [%1], 16;" :: "r"(smem_u32), "l"(gptr))
#define CP_COMMIT() asm volatile("cp.async.commit_group;")
#define CP_WAIT0()  asm volatile("cp.async.wait_group 0;")

// ---------------------------------------------------------------------------
// Pipelined single-fp16 GEMM: C[z] = W [M,K] @ B[z] [K,N].
// 128x128 tile, BK=32, 256 threads (8 warps 2x4).
// mode 0 -> g_q, mode 1 -> g_k/g_v, mode 2 -> fp32+bias to d_out.
// ---------------------------------------------------------------------------
#define BM 128
#define BN 128
#define BK 32
#define SA_STR 40
#define SB_STR 136
#define A_PLANE 10240
#define B_PLANE 8704
#define BUF_BYTES 18944   // A_PLANE + B_PLANE
#define GEMM_SMEM 66048   // sC epilogue (128*129*4) dominates

__global__ __launch_bounds__(256) void mma_gemm(int M, int N, int K, int mode,
                                                float* __restrict__ Ob,
                                                const float* __restrict__ bias0,
                                                const float* __restrict__ bias1)
{
    extern __shared__ char gsm[];
    unsigned* sC = (unsigned*)gsm;

    int z = blockIdx.z, s = z >> 4;
    const __half *Ap, *Bp;
    if (mode == 0) {
        Ap = g_wq  + s * 512 * 256;
        Bp = g_yq  + (long)z * 256 * 1024;
    } else if (mode == 1) {
        Ap = g_wkv + s * 1024 * 256;
        Bp = g_ykv + (long)z * 256 * 256;
    } else {
        Ap = g_wo  + s * 256 * 512;
        Bp = g_o   + (long)z * 512 * 1024;
    }

    int m0 = blockIdx.y * BM, n0 = blockIdx.x * BN;
    int tid = threadIdx.x, lane = tid & 31, wid = tid >> 5;
    int wm = wid >> 2, wn = wid & 3;

    float acc[4][4][4] = {};

    int arow = tid >> 2, acol = (tid & 3) * 8;
    int lr = lane & 15, lc = (lane >> 4) * 8;
    int brow2 = (lane & 7) + ((lane >> 3) & 1) * 8;
    int bcol2 = (lane >> 4) * 8;

    __half* pA[2] = {(__half*)gsm, (__half*)(gsm + BUF_BYTES)};
    __half* pB[2] = {(__half*)(gsm + A_PLANE), (__half*)(gsm + BUF_BYTES + A_PLANE)};

    int nk = K / BK;
    int bR[2], bC[2];
#pragma unroll
    for (int j = 0; j < 2; j++) { int sj = tid + 256 * j; bR[j] = sj >> 4; bC[j] = (sj & 15) * 8; }

    // prologue: buffer 0
    {
#pragma unroll
        for (int r = 0; r < 2; r++) {
            unsigned d0 = (unsigned)__cvta_generic_to_shared(&pA[0][(arow + 64 * r) * SA_STR + acol]);
            CP_ASYNC16(d0, &Ap[(long)(m0 + arow + 64 * r) * K + acol]);
        }
#pragma unroll
        for (int j = 0; j < 2; j++) {
            unsigned d = (unsigned)__cvta_generic_to_shared(&pB[0][bR[j] * SB_STR + bC[j]]);
            CP_ASYNC16(d, &Bp[(long)bR[j] * N + n0 + bC[j]]);
        }
        CP_COMMIT();
        CP_WAIT0();
        __syncthreads();
    }

    for (int i = 0; i < nk; i++) {
        int cur = i & 1, nxt = cur ^ 1;
        bool has_next = (i + 1 < nk);
        if (has_next) {
            int k0 = (i + 1) * BK;
#pragma unroll
            for (int r = 0; r < 2; r++) {
                unsigned d0 = (unsigned)__cvta_generic_to_shared(&pA[nxt][(arow + 64 * r) * SA_STR + acol]);
                CP_ASYNC16(d0, &Ap[(long)(m0 + arow + 64 * r) * K + k0 + acol]);
            }
#pragma unroll
            for (int j = 0; j < 2; j++) {
                unsigned d = (unsigned)__cvta_generic_to_shared(&pB[nxt][bR[j] * SB_STR + bC[j]]);
                CP_ASYNC16(d, &Bp[(long)(k0 + bR[j]) * N + n0 + bC[j]]);
            }
            CP_COMMIT();
        }

#pragma unroll
        for (int kk = 0; kk < BK; kk += 16) {
            unsigned a4[4][4], b4[2][4];
#pragma unroll
            for (int mi = 0; mi < 4; mi++)
                LDSM_X4(a4[mi], &pA[cur][(wm * 64 + mi * 16 + lr) * SA_STR + kk + lc]);
#pragma unroll
            for (int ni2 = 0; ni2 < 2; ni2++)
                LDSM_X4T(b4[ni2], &pB[cur][(kk + brow2) * SB_STR + wn * 32 + ni2 * 16 + bcol2]);
#pragma unroll
            for (int mi = 0; mi < 4; mi++)
#pragma unroll
                for (int ni = 0; ni < 4; ni++) {
                    unsigned* bb = b4[ni >> 1] + (ni & 1) * 2;
                    MMA_F16(acc[mi][ni], a4[mi], bb);
                }
        }

        if (has_next) CP_WAIT0();
        __syncthreads();
    }

    int r = lane >> 2, cc = (lane & 3) * 2;
    if (mode == 2) {
        const float* bias = s ? bias1 : bias0;
#pragma unroll
        for (int mi = 0; mi < 4; mi++)
#pragma unroll
            for (int ni = 0; ni < 4; ni++)
#pragma unroll
                for (int half = 0; half < 2; half++) {
                    int m = m0 + wm * 64 + mi * 16 + r + half * 8;
                    int n = n0 + wn * 32 + ni * 8 + cc;
                    float bv = bias[m];
                    float2 v = make_float2(acc[mi][ni][half * 2] + bv,
                                           acc[mi][ni][half * 2 + 1] + bv);
                    *(float2*)&Ob[((long)z * M + m) * N + n] = v;
                }
    } else {
#pragma unroll
        for (int mi = 0; mi < 4; mi++)
#pragma unroll
            for (int ni = 0; ni < 4; ni++)
#pragma unroll
                for (int half = 0; half < 2; half++) {
                    int ml = wm * 64 + mi * 16 + r + half * 8;
                    int nl = wn * 32 + ni * 8 + cc;
                    sC[ml * 129 + nl]     = (unsigned)__half_as_ushort(__float2half(acc[mi][ni][half * 2]));
                    sC[ml * 129 + nl + 1] = (unsigned)__half_as_ushort(__float2half(acc[mi][ni][half * 2 + 1]));
                }
        __syncthreads();

        int n = tid & 127, hh = tid >> 7;
        int mrow = m0 + hh * 64;
        __half* dsth;
        long base;
        if (mode == 0) {
            dsth = g_q;
            base = ((long)(z * 8 + (mrow >> 6)) * 1024 + n0 + n) * 64;
        } else if (mrow < 512) {
            dsth = g_k;
            base = ((long)(z * 8 + (mrow >> 6)) * 256 + n0 + n) * 64;
        } else {
            dsth = g_v;
            base = ((long)(z * 8 + ((mrow - 512) >> 6)) * 256 + n0 + n) * 64;
        }
#pragma unroll
        for (int d4 = 0; d4 < 64; d4 += 4) {
            uint2 t;
            t.x = (sC[(hh * 64 + d4 + 0) * 129 + n] & 0xFFFFu) | (sC[(hh * 64 + d4 + 1) * 129 + n] << 16);
            t.y = (sC[(hh * 64 + d4 + 2) * 129 + n] & 0xFFFFu) | (sC[(hh * 64 + d4 + 3) * 129 + n] << 16);
            *(uint2*)&dsth[base + d4] = t;
        }
    }
}

// ---------------------------------------------------------------------------
// Cross attention: all single-fp16 operands, 2 KV chunks + online softmax
// (unchanged from R16 best).
// ---------------------------------------------------------------------------
#define ATT_SMEM 55296

__global__ __launch_bounds__(256, 2) void attn_kernel()
{
    extern __shared__ char smx[];
    __half* Qs = (__half*)(smx);            // 128*72*2 = 18432
    __half* Ks = (__half*)(smx + 18432);
    __half* Vs = (__half*)(smx + 36864);
    float* Ost = (float*)smx;               // overlays Qs/Ks at end

    int bid = blockIdx.x;
    int qt = bid & 7, bhs = bid >> 3;
    int s = bhs >> 7, bh = bhs & 127, h = bh & 7, b = bh >> 3;

    const __half* qp = g_q + ((long)(s * 128 + bh) * 1024 + qt * 128) * 64;
    const __half* kp = g_k + (long)((1 - s) * 128 + bh) * 256 * 64;
    const __half* vp = g_v + (long)((1 - s) * 128 + bh) * 256 * 64;

    int tid = threadIdx.x, lane = tid & 31, w = tid >> 5;
    int r0 = w * 16;
    int krow = (lane & 7) + ((lane >> 4) << 3);

    for (int c = tid; c < 1024; c += 256) {
        int row = c >> 3, sg = (c & 7) * 8;
        *(uint4*)&Qs[row * 72 + sg] = *(const uint4*)&qp[row * 64 + sg];
    }

    float oreg[8][4] = {};
    float mrow0 = -1e30f, mrow1 = -1e30f, sum0 = 0.f, sum1 = 0.f;

    for (int ch = 0; ch < 2; ch++) {
        if (ch) __syncthreads();

        for (int c = tid; c < 1024; c += 256) {
            int row = c >> 3, sg = (c & 7) * 8;
            *(uint4*)&Ks[row * 72 + sg] = *(const uint4*)&kp[(ch * 128 + row) * 64 + sg];
            *(uint4*)&Vs[row * 72 + sg] = *(const uint4*)&vp[(ch * 128 + row) * 64 + sg];
        }
        __syncthreads();

        float sreg[16][4];
#pragma unroll
        for (int nt = 0; nt < 16; nt++) {
            sreg[nt][0] = 0.f; sreg[nt][1] = 0.f; sreg[nt][2] = 0.f; sreg[nt][3] = 0.f;
        }
        for (int kk = 0; kk < 4; kk++) {
            unsigned aq[4];
            int qoff = (r0 + (lane & 15)) * 72 + kk * 16 + (lane >> 4) * 8;
            LDSM_X4(aq, &Qs[qoff]);
            int koff = kk * 16 + ((lane >> 3) & 1) * 8;
#pragma unroll
            for (int nt4 = 0; nt4 < 4; nt4++) {
                unsigned khA[4], khB[4];
                LDSM_X4(khA, &Ks[((2 * nt4) * 16 + krow) * 72 + koff]);
                LDSM_X4(khB, &Ks[((2 * nt4 + 1) * 16 + krow) * 72 + koff]);
                MMA_F16(sreg[4 * nt4 + 0], aq, (khA + 0));
                MMA_F16(sreg[4 * nt4 + 1], aq, (khA + 2));
                MMA_F16(sreg[4 * nt4 + 2], aq, (khB + 0));
                MMA_F16(sreg[4 * nt4 + 3], aq, (khB + 2));
            }
        }

        {
            float mc0 = -1e30f, mc1 = -1e30f;
#pragma unroll
            for (int nt = 0; nt < 16; nt++) {
                mc0 = fmaxf(mc0, fmaxf(sreg[nt][0], sreg[nt][1]));
                mc1 = fmaxf(mc1, fmaxf(sreg[nt][2], sreg[nt][3]));
            }
            mc0 = fmaxf(mc0, __shfl_xor_sync(0xffffffffu, mc0, 1));
            mc0 = fmaxf(mc0, __shfl_xor_sync(0xffffffffu, mc0, 2));
            mc1 = fmaxf(mc1, __shfl_xor_sync(0xffffffffu, mc1, 1));
            mc1 = fmaxf(mc1, __shfl_xor_sync(0xffffffffu, mc1, 2));
            float mn0 = fmaxf(mrow0, mc0), mn1 = fmaxf(mrow1, mc1);
            float f0 = __expf(mrow0 - mn0), f1 = __expf(mrow1 - mn1);
            mrow0 = mn0; mrow1 = mn1;

            float cs0 = 0.f, cs1 = 0.f;
#pragma unroll
            for (int nt = 0; nt < 16; nt++) {
                float e0 = __expf(sreg[nt][0] - mn0); sreg[nt][0] = e0; cs0 += e0;
                float e1 = __expf(sreg[nt][1] - mn0); sreg[nt][1] = e1; cs0 += e1;
                float e2 = __expf(sreg[nt][2] - mn1); sreg[nt][2] = e2; cs1 += e2;
                float e3 = __expf(sreg[nt][3] - mn1); sreg[nt][3] = e3; cs1 += e3;
            }
            cs0 += __shfl_xor_sync(0xffffffffu, cs0, 1);
            cs0 += __shfl_xor_sync(0xffffffffu, cs0, 2);
            cs1 += __shfl_xor_sync(0xffffffffu, cs1, 1);
            cs1 += __shfl_xor_sync(0xffffffffu, cs1, 2);
            sum0 = sum0 * f0 + cs0;
            sum1 = sum1 * f1 + cs1;
#pragma unroll
            for (int nd = 0; nd < 8; nd++) {
                oreg[nd][0] *= f0; oreg[nd][1] *= f0;
                oreg[nd][2] *= f1; oreg[nd][3] *= f1;
            }
        }

#pragma unroll
        for (int kt = 0; kt < 8; kt++) {
            unsigned pa[4];
            {
                __half2 h0 = __floats2half2_rn(sreg[2 * kt][0],     sreg[2 * kt][1]);
                __half2 h1 = __floats2half2_rn(sreg[2 * kt][2],     sreg[2 * kt][3]);
                __half2 h2 = __floats2half2_rn(sreg[2 * kt + 1][0], sreg[2 * kt + 1][1]);
                __half2 h3 = __floats2half2_rn(sreg[2 * kt + 1][2], sreg[2 * kt + 1][3]);
                pa[0] = *(unsigned*)&h0; pa[1] = *(unsigned*)&h1;
                pa[2] = *(unsigned*)&h2; pa[3] = *(unsigned*)&h3;
            }
            int vrow = kt * 16 + (lane & 7) + ((lane >> 3) & 1) * 8;
            int vcol = (lane >> 4) << 3;
#pragma unroll
            for (int np = 0; np < 2; np++) {
                unsigned vhA[4], vhB[4];
                LDSM_X4T(vhA, &Vs[vrow * 72 + (2 * np) * 16 + vcol]);
                LDSM_X4T(vhB, &Vs[vrow * 72 + (2 * np + 1) * 16 + vcol]);
                MMA_F16(oreg[4 * np + 0], pa, (vhA + 0));
                MMA_F16(oreg[4 * np + 1], pa, (vhA + 2));
                MMA_F16(oreg[4 * np + 2], pa, (vhB + 0));
                MMA_F16(oreg[4 * np + 3], pa, (vhB + 2));
            }
        }
    }

    float inv0 = 1.f / sum0, inv1 = 1.f / sum1;
    __syncthreads();
    int r = lane >> 2, cc = (lane & 3) * 2;
#pragma unroll
    for (int nd = 0; nd < 8; nd++) {
        Ost[(r0 + r) * 65 + nd * 8 + cc]         = oreg[nd][0] * inv0;
        Ost[(r0 + r) * 65 + nd * 8 + cc + 1]     = oreg[nd][1] * inv0;
        Ost[(r0 + r + 8) * 65 + nd * 8 + cc]     = oreg[nd][2] * inv1;
        Ost[(r0 + r + 8) * 65 + nd * 8 + cc + 1] = oreg[nd][3] * inv1;
    }
    __syncthreads();

    __half* op = g_o + ((long)(s * 16 + b) * 512 + h * 64) * 1024 + qt * 128;
    int plane = lane * 4;
    for (int dd = w; dd < 64; dd += 8) {
        __half2 v0 = __floats2half2_rn(Ost[(plane + 0) * 65 + dd], Ost[(plane + 1) * 65 + dd]);
        __half2 v1 = __floats2half2_rn(Ost[(plane + 2) * 65 + dd], Ost[(plane + 3) * 65 + dd]);
        uint2 t = make_uint2(*(unsigned*)&v0, *(unsigned*)&v1);
        *(uint2*)&op[(long)dd * 1024 + plane] = t;
    }
}

// ---------------------------------------------------------------------------
// Orchestration.
// ---------------------------------------------------------------------------
extern "C" void kernel_launch(void* const* d_in, const int* in_sizes, int n_in,
                              void* d_out, int out_size)
{
    (void)in_sizes; (void)n_in; (void)out_size;
    #define F(i) ((const float*)d_in[i])

    cudaFuncSetAttribute(mma_gemm, cudaFuncAttributeMaxDynamicSharedMemorySize, GEMM_SMEM);
    cudaFuncSetAttribute(attn_kernel, cudaFuncAttributeMaxDynamicSharedMemorySize, ATT_SMEM);

    split_all_kernel<<<4096, 256>>>(F(7), F(19), F(13), F(25), F(26), F(28));

    int tot1 = 16 * 256 * 1024;
    int tot2 = 16 * 256 * 256;
    dwconv2_kernel<<<dim3((tot1 + 255) / 256, 2), 256>>>(
        F(0), F(1), F(2), F(3), F(4), F(5), F(6),
        F(14), F(15), F(16), F(17), F(18), 0, 1, 32);
    dwconv2_kernel<<<dim3((tot2 + 255) / 256, 2), 256>>>(
        F(0), F(1), F(8), F(9), F(10), F(11), F(12),
        F(20), F(21), F(22), F(23), F(24), 1, 2, 16);

    // q projection  [512,1024]
    mma_gemm<<<dim3(1024 / BN, 512 / BM, 32), 256, GEMM_SMEM>>>(512, 1024, 256, 0, nullptr, nullptr, nullptr);
    // kv projection [1024,256]
    mma_gemm<<<dim3(256 / BN, 1024 / BM, 32), 256, GEMM_SMEM>>>(1024, 256, 256, 1, nullptr, nullptr, nullptr);

    // attention
    attn_kernel<<<2048, 256, ATT_SMEM>>>();

    // out projection [256,1024]
    mma_gemm<<<dim3(1024 / BN, 256 / BM, 32), 256, GEMM_SMEM>>>(256, 1024, 512, 2, (float*)d_out, F(27), F(29));

    #undef F
}